// round 9
// baseline (speedup 1.0000x reference)
#include <cuda_runtime.h>
#include <cstdint>

#define NODES 100000
#define EMAX  1600000
#define F0 128
#define F1 64
#define F2 32
#define NB_SCAN 196          // ceil(100000/512)

// ---- scratch (static device globals: allocation-free) ----
__device__ int    d_degi[NODES];
__device__ unsigned long long d_scanstate[NB_SCAN];  // (sum<<2)|flag: 0=inv,1=partial,2=prefix
__device__ int    d_ticket;
__device__ int    d_off[NODES + 1];
__device__ int    d_pos[NODES];
__device__ int    d_csr[EMAX];
__device__ float  d_dinv[NODES];
__device__ float  d_g1[(size_t)NODES * F1];   // (x@W1)*dinv[src], fp32
__device__ float  d_h1[(size_t)NODES * F1];   // relu layer-1 output
__device__ float  d_g2[(size_t)NODES * F2];   // (h1@W2)*dinv[src]

struct SideStream {
    cudaStream_t s;
    cudaEvent_t evA, evB;
    SideStream() {
        cudaStreamCreateWithFlags(&s, cudaStreamNonBlocking);
        cudaEventCreateWithFlags(&evA, cudaEventDisableTiming);
        cudaEventCreateWithFlags(&evB, cudaEventDisableTiming);
    }
};
static SideStream g_ss;

// ================= zero degree + scan state =================
__global__ void k_zero(int n, int nb) {
    int i = blockIdx.x * blockDim.x + threadIdx.x;
    if (i < n) d_degi[i] = 0;
    if (i < nb) d_scanstate[i] = 0ULL;
    if (i == 0) d_ticket = 0;
}

// ================= degree histogram (4 edges/thread) =================
__global__ void k_count4(const int* __restrict__ dst, int e) {
    int i = (blockIdx.x * blockDim.x + threadIdx.x) * 4;
    if (i + 4 <= e) {
        int4 d = *(const int4*)(dst + i);
        atomicAdd(&d_degi[d.x], 1);
        atomicAdd(&d_degi[d.y], 1);
        atomicAdd(&d_degi[d.z], 1);
        atomicAdd(&d_degi[d.w], 1);
    } else {
        for (; i < e; ++i) atomicAdd(&d_degi[dst[i]], 1);
    }
}

// ================= single-pass scan: decoupled lookback =================
__global__ void k_scanLB(int n, int e) {
    __shared__ int sbid, spref;
    __shared__ int warpsum[16];
    int tid = threadIdx.x, lane = tid & 31, w = tid >> 5;
    if (tid == 0) sbid = atomicAdd(&d_ticket, 1);
    __syncthreads();
    int bid = sbid;
    int i = bid * 512 + tid;
    int deg = (i < n) ? d_degi[i] : 0;

    // warp-shuffle inclusive scan
    int incl = deg;
#pragma unroll
    for (int d = 1; d < 32; d <<= 1) {
        int t = __shfl_up_sync(0xffffffffu, incl, d);
        if (lane >= d) incl += t;
    }
    if (lane == 31) warpsum[w] = incl;
    __syncthreads();
    if (w == 0) {
        int s = (lane < 16) ? warpsum[lane] : 0;
#pragma unroll
        for (int d = 1; d < 16; d <<= 1) {
            int t = __shfl_up_sync(0xffffffffu, s, d);
            if (lane >= d) s += t;
        }
        if (lane < 16) warpsum[lane] = s;
    }
    __syncthreads();
    int total = warpsum[15];
    incl += (w > 0) ? warpsum[w - 1] : 0;

    // publish partial (block 0 publishes prefix directly)
    if (tid == 0)
        atomicExch(&d_scanstate[bid],
                   ((unsigned long long)total << 2) | (bid == 0 ? 2ULL : 1ULL));

    // warp-wide lookback
    if (w == 0) {
        int pref = 0;
        if (bid > 0) {
            int j = bid - 1;
            while (true) {
                int idx = j - (int)lane;
                unsigned long long st;
                if (idx >= 0) {
                    do { st = atomicAdd(&d_scanstate[idx], 0ULL); } while ((st & 3ULL) == 0ULL);
                } else {
                    st = 2ULL;  // virtual prefix 0
                }
                unsigned pmask = __ballot_sync(0xffffffffu, (st & 3ULL) == 2ULL);
                int val = (int)(st >> 2);
                int contrib;
                if (pmask) {
                    int k = __ffs(pmask) - 1;  // nearest prefix
                    contrib = (lane <= k) ? val : 0;
                } else {
                    contrib = val;
                }
#pragma unroll
                for (int o = 16; o; o >>= 1) contrib += __shfl_xor_sync(0xffffffffu, contrib, o);
                pref += contrib;
                if (pmask) break;
                j -= 32;
            }
            if (lane == 0)
                atomicExch(&d_scanstate[bid],
                           ((unsigned long long)(pref + total) << 2) | 2ULL);
        }
        if (lane == 0) spref = pref;
    }
    __syncthreads();

    int ex = spref + incl - deg;  // exclusive offset
    if (i < n) {
        d_off[i] = ex;
        d_pos[i] = ex;
        d_dinv[i] = rsqrtf(1.0f + (float)deg);  // +1 self-loop
    }
    if (i == n - 1) d_off[n] = e;
}

// ================= CSR fill (4 edges/thread) =================
__global__ void k_fill4(const int* __restrict__ src, const int* __restrict__ dst, int e) {
    int i = (blockIdx.x * blockDim.x + threadIdx.x) * 4;
    if (i + 4 <= e) {
        int4 s = *(const int4*)(src + i);
        int4 d = *(const int4*)(dst + i);
        int p0 = atomicAdd(&d_pos[d.x], 1); d_csr[p0] = s.x;
        int p1 = atomicAdd(&d_pos[d.y], 1); d_csr[p1] = s.y;
        int p2 = atomicAdd(&d_pos[d.z], 1); d_csr[p2] = s.z;
        int p3 = atomicAdd(&d_pos[d.w], 1); d_csr[p3] = s.w;
    } else {
        for (; i < e; ++i) {
            int d = dst[i];
            int p = atomicAdd(&d_pos[d], 1);
            d_csr[p] = src[i];
        }
    }
}

// ================= GEMM1: g1 = (x @ W1) * dinv (prescaled, fp32) ==========
// 128 nodes x 64 cols / block, 256 threads, 8x4 register tile, swizzled LDS.128
__global__ void k_gemm1(const float* __restrict__ x, const float* __restrict__ W, int n) {
    __shared__ float4 xs4[32 * 33];
    __shared__ float  ws[32][68];
    int tid = threadIdx.x;
    int tx = tid & 15, ty = tid >> 4;
    int nodeBase = blockIdx.x * 128;
    float acc[8][4] = {};

    for (int kc = 0; kc < F0; kc += 32) {
#pragma unroll
        for (int i = 0; i < 4; ++i) {
            int flat = i * 256 + tid;
            int row = flat >> 3;
            int c4  = flat & 7;
            int node = nodeBase + row;
            float4 v = make_float4(0.f, 0.f, 0.f, 0.f);
            if (node < n) v = __ldg((const float4*)(x + (size_t)node * F0 + kc + 4 * c4));
            int g = row >> 2, el = row & 3;
            const float vv[4] = {v.x, v.y, v.z, v.w};
#pragma unroll
            for (int j = 0; j < 4; ++j) {
                int k = 4 * c4 + j;
                float* p = (float*)&xs4[k * 33 + (g ^ ((k >> 2) & 7))];
                p[el] = vv[j];
            }
        }
#pragma unroll
        for (int i = 0; i < 2; ++i) {
            int flat = i * 256 + tid;
            int k = flat >> 4;
            int c4 = flat & 15;
            float4 w = __ldg((const float4*)(W + (size_t)(kc + k) * F1 + 4 * c4));
            *(float4*)&ws[k][4 * c4] = w;
        }
        __syncthreads();
#pragma unroll
        for (int k = 0; k < 32; ++k) {
            int swz = (k >> 2) & 7;
            float4 A0 = xs4[k * 33 + ((2 * ty) ^ swz)];
            float4 A1 = xs4[k * 33 + ((2 * ty + 1) ^ swz)];
            float4 B  = *(const float4*)&ws[k][4 * tx];
            float a[8] = {A0.x, A0.y, A0.z, A0.w, A1.x, A1.y, A1.z, A1.w};
            float b[4] = {B.x, B.y, B.z, B.w};
#pragma unroll
            for (int m = 0; m < 8; ++m)
#pragma unroll
                for (int q = 0; q < 4; ++q)
                    acc[m][q] += a[m] * b[q];
        }
        __syncthreads();
    }

#pragma unroll
    for (int m = 0; m < 8; ++m) {
        int node = nodeBase + 8 * ty + m;
        if (node < n) {
            float dv = __ldg(&d_dinv[node]);
            float4 o = make_float4(acc[m][0] * dv, acc[m][1] * dv,
                                   acc[m][2] * dv, acc[m][3] * dv);
            *(float4*)(d_g1 + (size_t)node * F1 + 4 * tx) = o;
        }
    }
}

// ================= Gather layer1 =================
// h1[d] = relu(dinv[d]*(sum_s g1[s] + g1[d]) + b1) ; g1 prescaled by dinv[s].
// 16 lanes/node, float4 per lane, unrolled x4.
__global__ void k_gather1(const float* __restrict__ b1, int n) {
    int node = (blockIdx.x * blockDim.x + threadIdx.x) >> 4;
    int lane = threadIdx.x & 15;
    if (node >= n) return;
    const float4* g1 = (const float4*)d_g1;  // 16 float4 per row
    float4 acc = __ldg(&g1[(size_t)node * 16 + lane]);  // self loop
    int beg = __ldg(&d_off[node]), end = __ldg(&d_off[node + 1]);
    int j = beg;
    for (; j + 4 <= end; j += 4) {
        int s0 = __ldg(&d_csr[j + 0]);
        int s1 = __ldg(&d_csr[j + 1]);
        int s2 = __ldg(&d_csr[j + 2]);
        int s3 = __ldg(&d_csr[j + 3]);
        float4 v0 = __ldg(&g1[(size_t)s0 * 16 + lane]);
        float4 v1 = __ldg(&g1[(size_t)s1 * 16 + lane]);
        float4 v2 = __ldg(&g1[(size_t)s2 * 16 + lane]);
        float4 v3 = __ldg(&g1[(size_t)s3 * 16 + lane]);
        acc.x += (v0.x + v1.x) + (v2.x + v3.x);
        acc.y += (v0.y + v1.y) + (v2.y + v3.y);
        acc.z += (v0.z + v1.z) + (v2.z + v3.z);
        acc.w += (v0.w + v1.w) + (v2.w + v3.w);
    }
    for (; j < end; ++j) {
        int s = __ldg(&d_csr[j]);
        float4 v = __ldg(&g1[(size_t)s * 16 + lane]);
        acc.x += v.x; acc.y += v.y; acc.z += v.z; acc.w += v.w;
    }
    float dv = __ldg(&d_dinv[node]);
    float4 bb = __ldg(&((const float4*)b1)[lane]);
    float4 h;
    h.x = fmaxf(fmaf(acc.x, dv, bb.x), 0.f);
    h.y = fmaxf(fmaf(acc.y, dv, bb.y), 0.f);
    h.z = fmaxf(fmaf(acc.z, dv, bb.z), 0.f);
    h.w = fmaxf(fmaf(acc.w, dv, bb.w), 0.f);
    ((float4*)d_h1)[(size_t)node * 16 + lane] = h;
}

// ================= GEMM2: g2 = (h1 @ W2) * dinv (fp32) =================
__global__ void k_gemm2(const float* __restrict__ W2, int n) {
    __shared__ float4 xs4[64 * 33];
    __shared__ float  ws[64][36];
    int tid = threadIdx.x;
    int tx = tid & 15, ty = tid >> 4;
    int nodeBase = blockIdx.x * 128;
    float acc[8][2] = {};

#pragma unroll
    for (int i = 0; i < 8; ++i) {
        int flat = i * 256 + tid;
        int row = flat >> 4;
        int c4  = flat & 15;
        int node = nodeBase + row;
        float4 v = make_float4(0.f, 0.f, 0.f, 0.f);
        if (node < n) v = __ldg((const float4*)(d_h1 + (size_t)node * F1 + 4 * c4));
        int g = row >> 2, el = row & 3;
        const float vv[4] = {v.x, v.y, v.z, v.w};
#pragma unroll
        for (int j = 0; j < 4; ++j) {
            int k = 4 * c4 + j;
            float* p = (float*)&xs4[k * 33 + (g ^ ((k >> 2) & 7))];
            p[el] = vv[j];
        }
    }
#pragma unroll
    for (int i = 0; i < 2; ++i) {
        int flat = i * 256 + tid;
        int k = flat >> 3;
        int c4 = flat & 7;
        float4 w = __ldg((const float4*)(W2 + (size_t)k * F2 + 4 * c4));
        *(float4*)&ws[k][4 * c4] = w;
    }
    __syncthreads();

#pragma unroll
    for (int k = 0; k < 64; ++k) {
        int swz = (k >> 2) & 7;
        float4 A0 = xs4[k * 33 + ((2 * ty) ^ swz)];
        float4 A1 = xs4[k * 33 + ((2 * ty + 1) ^ swz)];
        float b0 = ws[k][2 * tx + 0];
        float b1 = ws[k][2 * tx + 1];
        float a[8] = {A0.x, A0.y, A0.z, A0.w, A1.x, A1.y, A1.z, A1.w};
#pragma unroll
        for (int m = 0; m < 8; ++m) {
            acc[m][0] += a[m] * b0;
            acc[m][1] += a[m] * b1;
        }
    }

#pragma unroll
    for (int m = 0; m < 8; ++m) {
        int node = nodeBase + 8 * ty + m;
        if (node < n) {
            float dv = __ldg(&d_dinv[node]);
            float2 o = make_float2(acc[m][0] * dv, acc[m][1] * dv);
            *(float2*)(d_g2 + (size_t)node * F2 + 2 * tx) = o;
        }
    }
}

// ================= Gather layer2 =================
// out[d] = dinv[d]*(sum_s g2[s] + g2[d]) + b2 ; g2 prescaled by dinv[s].
// 16 lanes/node, float2 per lane (128B row = 1 wavefront/edge), unrolled x4.
__global__ void k_gather2(const float* __restrict__ b2, float* __restrict__ out, int n) {
    int node = (blockIdx.x * blockDim.x + threadIdx.x) >> 4;
    int lane = threadIdx.x & 15;
    if (node >= n) return;
    const float2* g2 = (const float2*)d_g2;  // 16 float2 per row
    float2 acc = __ldg(&g2[(size_t)node * 16 + lane]);  // self loop
    int beg = __ldg(&d_off[node]), end = __ldg(&d_off[node + 1]);
    int j = beg;
    for (; j + 4 <= end; j += 4) {
        int s0 = __ldg(&d_csr[j + 0]);
        int s1 = __ldg(&d_csr[j + 1]);
        int s2 = __ldg(&d_csr[j + 2]);
        int s3 = __ldg(&d_csr[j + 3]);
        float2 v0 = __ldg(&g2[(size_t)s0 * 16 + lane]);
        float2 v1 = __ldg(&g2[(size_t)s1 * 16 + lane]);
        float2 v2 = __ldg(&g2[(size_t)s2 * 16 + lane]);
        float2 v3 = __ldg(&g2[(size_t)s3 * 16 + lane]);
        acc.x += (v0.x + v1.x) + (v2.x + v3.x);
        acc.y += (v0.y + v1.y) + (v2.y + v3.y);
    }
    for (; j < end; ++j) {
        int s = __ldg(&d_csr[j]);
        float2 v = __ldg(&g2[(size_t)s * 16 + lane]);
        acc.x += v.x;
        acc.y += v.y;
    }
    float dv = __ldg(&d_dinv[node]);
    float2 bb = __ldg(&((const float2*)b2)[lane]);
    float2 o;
    o.x = fmaf(acc.x, dv, bb.x);
    o.y = fmaf(acc.y, dv, bb.y);
    ((float2*)out)[(size_t)node * 16 + lane] = o;
}

extern "C" void kernel_launch(void* const* d_in, const int* in_sizes, int n_in,
                              void* d_out, int out_size) {
    const float* x  = (const float*)d_in[0];
    const int*   ei = (const int*)d_in[1];
    const float* W1 = (const float*)d_in[2];
    const float* b1 = (const float*)d_in[3];
    const float* W2 = (const float*)d_in[4];
    const float* b2 = (const float*)d_in[5];
    float* out = (float*)d_out;

    int n = in_sizes[0] / F0;   // 100000
    int e = in_sizes[1] / 2;    // 1600000
    const int* src = ei;
    const int* dst = ei + e;
    int nb = (n + 511) / 512;   // 196
    int eg4 = (e / 4 + 255) / 256 + 1;  // grid for 4-edges/thread kernels

    // CSR degree + offsets on main stream
    k_zero<<<(n + 255) / 256, 256>>>(n, nb);
    k_count4<<<eg4, 256>>>(dst, e);
    k_scanLB<<<nb, 512>>>(n, e);

    // Fork: gemm1 (needs dinv only) overlaps fill (atomic-bound).
    cudaEventRecord(g_ss.evA, 0);
    cudaStreamWaitEvent(g_ss.s, g_ss.evA, 0);
    k_gemm1<<<(n + 127) / 128, 256, 0, g_ss.s>>>(x, W1, n);
    cudaEventRecord(g_ss.evB, g_ss.s);

    k_fill4<<<eg4, 256>>>(src, dst, e);

    cudaStreamWaitEvent(0, g_ss.evB, 0);

    k_gather1<<<(n + 15) / 16, 256>>>(b1, n);
    k_gemm2<<<(n + 127) / 128, 256>>>(W2, n);
    k_gather2<<<(n + 15) / 16, 256>>>(b2, out, n);
}

// round 11
// speedup vs baseline: 1.0467x; 1.0467x over previous
#include <cuda_runtime.h>
#include <cstdint>

#define NODES 100000
#define EMAX  1600000
#define F0 128
#define F1 64
#define F2 32
#define NB_SCAN 196          // ceil(100000/512)

// ---- scratch (static device globals: allocation-free) ----
__device__ int    d_degi[NODES];
__device__ unsigned long long d_scanstate[NB_SCAN];  // (sum<<2)|flag: 0=inv,1=partial,2=prefix
__device__ int    d_ticket;
__device__ int    d_off[NODES + 1];
__device__ int    d_pos[NODES];
__device__ int    d_csr[EMAX];
__device__ float  d_dinv[NODES];
__device__ float  d_g1[(size_t)NODES * F1];   // (x@W1)*dinv[src]
__device__ float  d_h1[(size_t)NODES * F1];   // relu layer-1 output
__device__ float  d_g2[(size_t)NODES * F2];   // (h1@W2)*dinv[src]

struct SideStream {
    cudaStream_t s;
    cudaEvent_t evA, evB;
    SideStream() {
        cudaStreamCreateWithFlags(&s, cudaStreamNonBlocking);
        cudaEventCreateWithFlags(&evA, cudaEventDisableTiming);
        cudaEventCreateWithFlags(&evB, cudaEventDisableTiming);
    }
};
static SideStream g_ss;

// ================= zero degree + scan state =================
__global__ void k_zero(int n, int nb) {
    int i = blockIdx.x * blockDim.x + threadIdx.x;
    if (i < n) d_degi[i] = 0;
    if (i < nb) d_scanstate[i] = 0ULL;
    if (i == 0) d_ticket = 0;
}

// ================= degree histogram (4 edges/thread) =================
__global__ void k_count4(const int* __restrict__ dst, int e) {
    int i = (blockIdx.x * blockDim.x + threadIdx.x) * 4;
    if (i + 4 <= e) {
        int4 d = *(const int4*)(dst + i);
        atomicAdd(&d_degi[d.x], 1);
        atomicAdd(&d_degi[d.y], 1);
        atomicAdd(&d_degi[d.z], 1);
        atomicAdd(&d_degi[d.w], 1);
    } else {
        for (; i < e; ++i) atomicAdd(&d_degi[dst[i]], 1);
    }
}

// ================= single-pass scan: decoupled lookback =================
__global__ void k_scanLB(int n, int e) {
    __shared__ int sbid, spref;
    __shared__ int warpsum[16];
    int tid = threadIdx.x, lane = tid & 31, w = tid >> 5;
    if (tid == 0) sbid = atomicAdd(&d_ticket, 1);
    __syncthreads();
    int bid = sbid;
    int i = bid * 512 + tid;
    int deg = (i < n) ? d_degi[i] : 0;

    int incl = deg;
#pragma unroll
    for (int d = 1; d < 32; d <<= 1) {
        int t = __shfl_up_sync(0xffffffffu, incl, d);
        if (lane >= d) incl += t;
    }
    if (lane == 31) warpsum[w] = incl;
    __syncthreads();
    if (w == 0) {
        int s = (lane < 16) ? warpsum[lane] : 0;
#pragma unroll
        for (int d = 1; d < 16; d <<= 1) {
            int t = __shfl_up_sync(0xffffffffu, s, d);
            if (lane >= d) s += t;
        }
        if (lane < 16) warpsum[lane] = s;
    }
    __syncthreads();
    int total = warpsum[15];
    incl += (w > 0) ? warpsum[w - 1] : 0;

    if (tid == 0)
        atomicExch(&d_scanstate[bid],
                   ((unsigned long long)total << 2) | (bid == 0 ? 2ULL : 1ULL));

    if (w == 0) {
        int pref = 0;
        if (bid > 0) {
            int j = bid - 1;
            while (true) {
                int idx = j - (int)lane;
                unsigned long long st;
                if (idx >= 0) {
                    do { st = atomicAdd(&d_scanstate[idx], 0ULL); } while ((st & 3ULL) == 0ULL);
                } else {
                    st = 2ULL;
                }
                unsigned pmask = __ballot_sync(0xffffffffu, (st & 3ULL) == 2ULL);
                int val = (int)(st >> 2);
                int contrib;
                if (pmask) {
                    int k = __ffs(pmask) - 1;
                    contrib = (lane <= k) ? val : 0;
                } else {
                    contrib = val;
                }
#pragma unroll
                for (int o = 16; o; o >>= 1) contrib += __shfl_xor_sync(0xffffffffu, contrib, o);
                pref += contrib;
                if (pmask) break;
                j -= 32;
            }
            if (lane == 0)
                atomicExch(&d_scanstate[bid],
                           ((unsigned long long)(pref + total) << 2) | 2ULL);
        }
        if (lane == 0) spref = pref;
    }
    __syncthreads();

    int ex = spref + incl - deg;
    if (i < n) {
        d_off[i] = ex;
        d_pos[i] = ex;
        d_dinv[i] = rsqrtf(1.0f + (float)deg);
    }
    if (i == n - 1) d_off[n] = e;
}

// ================= CSR fill (4 edges/thread) =================
__global__ void k_fill4(const int* __restrict__ src, const int* __restrict__ dst, int e) {
    int i = (blockIdx.x * blockDim.x + threadIdx.x) * 4;
    if (i + 4 <= e) {
        int4 s = *(const int4*)(src + i);
        int4 d = *(const int4*)(dst + i);
        int p0 = atomicAdd(&d_pos[d.x], 1); d_csr[p0] = s.x;
        int p1 = atomicAdd(&d_pos[d.y], 1); d_csr[p1] = s.y;
        int p2 = atomicAdd(&d_pos[d.z], 1); d_csr[p2] = s.z;
        int p3 = atomicAdd(&d_pos[d.w], 1); d_csr[p3] = s.w;
    } else {
        for (; i < e; ++i) {
            int d = dst[i];
            int p = atomicAdd(&d_pos[d], 1);
            d_csr[p] = src[i];
        }
    }
}

// ================= tf32 helpers =================
__device__ __forceinline__ float f2tf32(float f) {
    unsigned u;
    asm("cvt.rna.tf32.f32 %0, %1;\n" : "=r"(u) : "f"(f));
    return __uint_as_float(u);
}

__device__ __forceinline__ void mma_tf32(float* d,
                                         const unsigned* a, const unsigned* b,
                                         const float* c) {
    asm volatile(
        "mma.sync.aligned.m16n8k8.row.col.f32.tf32.tf32.f32 "
        "{%0,%1,%2,%3}, {%4,%5,%6,%7}, {%8,%9}, {%10,%11,%12,%13};\n"
        : "=f"(d[0]), "=f"(d[1]), "=f"(d[2]), "=f"(d[3])
        : "r"(a[0]), "r"(a[1]), "r"(a[2]), "r"(a[3]),
          "r"(b[0]), "r"(b[1]),
          "f"(c[0]), "f"(c[1]), "f"(c[2]), "f"(c[3]));
}

// ================= GEMM1 (tf32 mma.sync): g1 = (x @ W1) * dinv =============
// 128 nodes x 64 cols / block; 8 warps in 4(m) x 2(n), each 32x32 via
// 2(m) x 4(n) m16n8k8 atoms. K staged in chunks of 32; inputs cvt'd to tf32
// at staging. Accumulators written straight to gmem (no smem C round-trip).
//
// PTX ISA m16n8k8 tf32 fragment layout (g = lane>>2, t = lane&3):
//   A (16x8 row):  a0=(g,t)  a1=(g+8,t)  a2=(g,t+4)  a3=(g+8,t+4)
//   B (8x8 col):   b0=(t,g)  b1=(t+4,g)          [row=k, col=n]
//   C (16x8):      c0=(g,2t) c1=(g,2t+1) c2=(g+8,2t) c3=(g+8,2t+1)
#define G1_LDA 36   // xs stride: bank = 4*row + k (mod 32), conflict-free
#define G1_LDB 72   // ws stride: bank = 8*k + n (mod 32), conflict-free
__global__ __launch_bounds__(256) void k_gemm1(const float* __restrict__ x,
                                               const float* __restrict__ W, int n) {
    __shared__ float xs[128 * G1_LDA];  // 128 rows x 32 k
    __shared__ float ws[32 * G1_LDB];   // 32 k x 64 n
    int tid = threadIdx.x;
    int w = tid >> 5, lane = tid & 31;
    int g = lane >> 2, t = lane & 3;
    int nodeBase = blockIdx.x * 128;
    int mw = (w & 3) * 32;
    int nw = (w >> 2) * 32;

    float acc[2][4][4] = {};

    for (int kc = 0; kc < F0; kc += 32) {
        // stage x chunk (128 x 32), cvt to tf32
#pragma unroll
        for (int i = 0; i < 4; ++i) {
            int flat = i * 256 + tid;       // 0..1023
            int row = flat >> 3;            // 0..127
            int c4  = flat & 7;             // 0..7
            int node = nodeBase + row;
            float4 v = make_float4(0.f, 0.f, 0.f, 0.f);
            if (node < n) v = __ldg((const float4*)(x + (size_t)node * F0 + kc + 4 * c4));
            v.x = f2tf32(v.x); v.y = f2tf32(v.y);
            v.z = f2tf32(v.z); v.w = f2tf32(v.w);
            *(float4*)&xs[row * G1_LDA + 4 * c4] = v;
        }
        // stage W chunk (32 x 64), cvt to tf32
#pragma unroll
        for (int i = 0; i < 2; ++i) {
            int flat = i * 256 + tid;       // 0..511
            int row = flat >> 4;            // 0..31 (k)
            int c4  = flat & 15;            // 0..15
            float4 v = __ldg((const float4*)(W + (size_t)(kc + row) * F1 + 4 * c4));
            v.x = f2tf32(v.x); v.y = f2tf32(v.y);
            v.z = f2tf32(v.z); v.w = f2tf32(v.w);
            *(float4*)&ws[row * G1_LDB + 4 * c4] = v;
        }
        __syncthreads();

#pragma unroll
        for (int ks = 0; ks < 4; ++ks) {
            int k0 = ks * 8;
            unsigned a[2][4];
#pragma unroll
            for (int m = 0; m < 2; ++m) {
                const float* base = &xs[(mw + 16 * m + g) * G1_LDA + k0 + t];
                a[m][0] = __float_as_uint(base[0]);
                a[m][1] = __float_as_uint(base[8 * G1_LDA]);
                a[m][2] = __float_as_uint(base[4]);
                a[m][3] = __float_as_uint(base[8 * G1_LDA + 4]);
            }
#pragma unroll
            for (int nn = 0; nn < 4; ++nn) {
                int n0 = nw + 8 * nn;
                unsigned b[2];
                b[0] = __float_as_uint(ws[(k0 + t) * G1_LDB + n0 + g]);
                b[1] = __float_as_uint(ws[(k0 + t + 4) * G1_LDB + n0 + g]);
                mma_tf32(acc[0][nn], a[0], b, acc[0][nn]);
                mma_tf32(acc[1][nn], a[1], b, acc[1][nn]);
            }
        }
        __syncthreads();
    }

    // epilogue: registers -> gmem with dinv scaling
#pragma unroll
    for (int m = 0; m < 2; ++m) {
        int r0 = nodeBase + mw + 16 * m + g;
        int r1 = r0 + 8;
        float dv0 = (r0 < n) ? __ldg(&d_dinv[r0]) : 0.f;
        float dv1 = (r1 < n) ? __ldg(&d_dinv[r1]) : 0.f;
#pragma unroll
        for (int nn = 0; nn < 4; ++nn) {
            int col = nw + 8 * nn + 2 * t;
            if (r0 < n) {
                float2 o = make_float2(acc[m][nn][0] * dv0, acc[m][nn][1] * dv0);
                *(float2*)(d_g1 + (size_t)r0 * F1 + col) = o;
            }
            if (r1 < n) {
                float2 o = make_float2(acc[m][nn][2] * dv1, acc[m][nn][3] * dv1);
                *(float2*)(d_g1 + (size_t)r1 * F1 + col) = o;
            }
        }
    }
}

// ================= Gather layer1 =================
// h1[d] = relu(dinv[d]*(sum_s g1[s] + g1[d]) + b1) ; g1 prescaled by dinv[s].
__global__ void k_gather1(const float* __restrict__ b1, int n) {
    int node = (blockIdx.x * blockDim.x + threadIdx.x) >> 4;
    int lane = threadIdx.x & 15;
    if (node >= n) return;
    const float4* g1 = (const float4*)d_g1;
    float4 acc = __ldg(&g1[(size_t)node * 16 + lane]);
    int beg = __ldg(&d_off[node]), end = __ldg(&d_off[node + 1]);
    int j = beg;
    for (; j + 4 <= end; j += 4) {
        int s0 = __ldg(&d_csr[j + 0]);
        int s1 = __ldg(&d_csr[j + 1]);
        int s2 = __ldg(&d_csr[j + 2]);
        int s3 = __ldg(&d_csr[j + 3]);
        float4 v0 = __ldg(&g1[(size_t)s0 * 16 + lane]);
        float4 v1 = __ldg(&g1[(size_t)s1 * 16 + lane]);
        float4 v2 = __ldg(&g1[(size_t)s2 * 16 + lane]);
        float4 v3 = __ldg(&g1[(size_t)s3 * 16 + lane]);
        acc.x += (v0.x + v1.x) + (v2.x + v3.x);
        acc.y += (v0.y + v1.y) + (v2.y + v3.y);
        acc.z += (v0.z + v1.z) + (v2.z + v3.z);
        acc.w += (v0.w + v1.w) + (v2.w + v3.w);
    }
    for (; j < end; ++j) {
        int s = __ldg(&d_csr[j]);
        float4 v = __ldg(&g1[(size_t)s * 16 + lane]);
        acc.x += v.x; acc.y += v.y; acc.z += v.z; acc.w += v.w;
    }
    float dv = __ldg(&d_dinv[node]);
    float4 bb = __ldg(&((const float4*)b1)[lane]);
    float4 h;
    h.x = fmaxf(fmaf(acc.x, dv, bb.x), 0.f);
    h.y = fmaxf(fmaf(acc.y, dv, bb.y), 0.f);
    h.z = fmaxf(fmaf(acc.z, dv, bb.z), 0.f);
    h.w = fmaxf(fmaf(acc.w, dv, bb.w), 0.f);
    ((float4*)d_h1)[(size_t)node * 16 + lane] = h;
}

// ================= GEMM2 (fp32 SIMT, proven): g2 = (h1 @ W2) * dinv =======
__global__ void k_gemm2(const float* __restrict__ W2, int n) {
    __shared__ float4 xs4[64 * 33];
    __shared__ float  ws[64][36];
    int tid = threadIdx.x;
    int tx = tid & 15, ty = tid >> 4;
    int nodeBase = blockIdx.x * 128;
    float acc[8][2] = {};

#pragma unroll
    for (int i = 0; i < 8; ++i) {
        int flat = i * 256 + tid;
        int row = flat >> 4;
        int c4  = flat & 15;
        int node = nodeBase + row;
        float4 v = make_float4(0.f, 0.f, 0.f, 0.f);
        if (node < n) v = __ldg((const float4*)(d_h1 + (size_t)node * F1 + 4 * c4));
        int g = row >> 2, el = row & 3;
        const float vv[4] = {v.x, v.y, v.z, v.w};
#pragma unroll
        for (int j = 0; j < 4; ++j) {
            int k = 4 * c4 + j;
            float* p = (float*)&xs4[k * 33 + (g ^ ((k >> 2) & 7))];
            p[el] = vv[j];
        }
    }
#pragma unroll
    for (int i = 0; i < 2; ++i) {
        int flat = i * 256 + tid;
        int k = flat >> 3;
        int c4 = flat & 7;
        float4 w = __ldg((const float4*)(W2 + (size_t)k * F2 + 4 * c4));
        *(float4*)&ws[k][4 * c4] = w;
    }
    __syncthreads();

#pragma unroll
    for (int k = 0; k < 64; ++k) {
        int swz = (k >> 2) & 7;
        float4 A0 = xs4[k * 33 + ((2 * ty) ^ swz)];
        float4 A1 = xs4[k * 33 + ((2 * ty + 1) ^ swz)];
        float b0 = ws[k][2 * tx + 0];
        float b1 = ws[k][2 * tx + 1];
        float a[8] = {A0.x, A0.y, A0.z, A0.w, A1.x, A1.y, A1.z, A1.w};
#pragma unroll
        for (int m = 0; m < 8; ++m) {
            acc[m][0] += a[m] * b0;
            acc[m][1] += a[m] * b1;
        }
    }

#pragma unroll
    for (int m = 0; m < 8; ++m) {
        int node = nodeBase + 8 * ty + m;
        if (node < n) {
            float dv = __ldg(&d_dinv[node]);
            float2 o = make_float2(acc[m][0] * dv, acc[m][1] * dv);
            *(float2*)(d_g2 + (size_t)node * F2 + 2 * tx) = o;
        }
    }
}

// ================= Gather layer2 =================
// out[d] = dinv[d]*(sum_s g2[s] + g2[d]) + b2 ; g2 prescaled by dinv[s].
__global__ void k_gather2(const float* __restrict__ b2, float* __restrict__ out, int n) {
    int node = (blockIdx.x * blockDim.x + threadIdx.x) >> 4;
    int lane = threadIdx.x & 15;
    if (node >= n) return;
    const float2* g2 = (const float2*)d_g2;
    float2 acc = __ldg(&g2[(size_t)node * 16 + lane]);
    int beg = __ldg(&d_off[node]), end = __ldg(&d_off[node + 1]);
    int j = beg;
    for (; j + 4 <= end; j += 4) {
        int s0 = __ldg(&d_csr[j + 0]);
        int s1 = __ldg(&d_csr[j + 1]);
        int s2 = __ldg(&d_csr[j + 2]);
        int s3 = __ldg(&d_csr[j + 3]);
        float2 v0 = __ldg(&g2[(size_t)s0 * 16 + lane]);
        float2 v1 = __ldg(&g2[(size_t)s1 * 16 + lane]);
        float2 v2 = __ldg(&g2[(size_t)s2 * 16 + lane]);
        float2 v3 = __ldg(&g2[(size_t)s3 * 16 + lane]);
        acc.x += (v0.x + v1.x) + (v2.x + v3.x);
        acc.y += (v0.y + v1.y) + (v2.y + v3.y);
    }
    for (; j < end; ++j) {
        int s = __ldg(&d_csr[j]);
        float2 v = __ldg(&g2[(size_t)s * 16 + lane]);
        acc.x += v.x;
        acc.y += v.y;
    }
    float dv = __ldg(&d_dinv[node]);
    float2 bb = __ldg(&((const float2*)b2)[lane]);
    float2 o;
    o.x = fmaf(acc.x, dv, bb.x);
    o.y = fmaf(acc.y, dv, bb.y);
    ((float2*)out)[(size_t)node * 16 + lane] = o;
}

extern "C" void kernel_launch(void* const* d_in, const int* in_sizes, int n_in,
                              void* d_out, int out_size) {
    const float* x  = (const float*)d_in[0];
    const int*   ei = (const int*)d_in[1];
    const float* W1 = (const float*)d_in[2];
    const float* b1 = (const float*)d_in[3];
    const float* W2 = (const float*)d_in[4];
    const float* b2 = (const float*)d_in[5];
    float* out = (float*)d_out;

    int n = in_sizes[0] / F0;   // 100000
    int e = in_sizes[1] / 2;    // 1600000
    const int* src = ei;
    const int* dst = ei + e;
    int nb = (n + 511) / 512;   // 196
    int eg4 = (e / 4 + 255) / 256 + 1;

    // CSR degree + offsets
    k_zero<<<(n + 255) / 256, 256>>>(n, nb);
    k_count4<<<eg4, 256>>>(dst, e);
    k_scanLB<<<nb, 512>>>(n, e);

    // Fork: gemm1 (needs dinv only) overlaps fill (atomic-bound).
    cudaEventRecord(g_ss.evA, 0);
    cudaStreamWaitEvent(g_ss.s, g_ss.evA, 0);
    k_gemm1<<<(n + 127) / 128, 256, 0, g_ss.s>>>(x, W1, n);
    cudaEventRecord(g_ss.evB, g_ss.s);

    k_fill4<<<eg4, 256>>>(src, dst, e);

    cudaStreamWaitEvent(0, g_ss.evB, 0);

    k_gather1<<<(n + 15) / 16, 256>>>(b1, n);
    k_gemm2<<<(n + 127) / 128, 256>>>(W2, n);
    k_gather2<<<(n + 15) / 16, 256>>>(b2, out, n);
}

// round 15
// speedup vs baseline: 1.0666x; 1.0190x over previous
#include <cuda_runtime.h>
#include <cstdint>

#define NODES 100000
#define EMAX  1600000
#define F0 128
#define F1 64
#define F2 32
#define NB_SCAN 196          // ceil(100000/512)

// ---- scratch (static device globals: allocation-free) ----
__device__ int    d_degi[NODES];
__device__ unsigned long long d_scanstate[NB_SCAN];  // (sum<<2)|flag: 0=inv,1=partial,2=prefix
__device__ int    d_ticket;
__device__ int    d_off[NODES + 1];
__device__ int    d_pos[NODES];
__device__ int    d_csr[EMAX];
__device__ float  d_dinv[NODES];
__device__ float  d_g1[(size_t)NODES * F1];   // x@W1  (UNSCALED — dinv applied in gather1)
__device__ float  d_h1[(size_t)NODES * F1];   // relu layer-1 output
__device__ float  d_g2[(size_t)NODES * F2];   // (h1@W2)*dinv[src]

struct SideStream {
    cudaStream_t s;
    cudaEvent_t evA, evB;
    SideStream() {
        cudaStreamCreateWithFlags(&s, cudaStreamNonBlocking);
        cudaEventCreateWithFlags(&evA, cudaEventDisableTiming);
        cudaEventCreateWithFlags(&evB, cudaEventDisableTiming);
    }
};
static SideStream g_ss;

// ================= zero degree + scan state =================
__global__ void k_zero(int n, int nb) {
    int i = blockIdx.x * blockDim.x + threadIdx.x;
    if (i < n) d_degi[i] = 0;
    if (i < nb) d_scanstate[i] = 0ULL;
    if (i == 0) d_ticket = 0;
}

// ================= degree histogram (4 edges/thread) =================
__global__ void k_count4(const int* __restrict__ dst, int e) {
    int i = (blockIdx.x * blockDim.x + threadIdx.x) * 4;
    if (i + 4 <= e) {
        int4 d = *(const int4*)(dst + i);
        atomicAdd(&d_degi[d.x], 1);
        atomicAdd(&d_degi[d.y], 1);
        atomicAdd(&d_degi[d.z], 1);
        atomicAdd(&d_degi[d.w], 1);
    } else {
        for (; i < e; ++i) atomicAdd(&d_degi[dst[i]], 1);
    }
}

// ================= single-pass scan: decoupled lookback =================
__global__ void k_scanLB(int n, int e) {
    __shared__ int sbid, spref;
    __shared__ int warpsum[16];
    int tid = threadIdx.x, lane = tid & 31, w = tid >> 5;
    if (tid == 0) sbid = atomicAdd(&d_ticket, 1);
    __syncthreads();
    int bid = sbid;
    int i = bid * 512 + tid;
    int deg = (i < n) ? d_degi[i] : 0;

    int incl = deg;
#pragma unroll
    for (int d = 1; d < 32; d <<= 1) {
        int t = __shfl_up_sync(0xffffffffu, incl, d);
        if (lane >= d) incl += t;
    }
    if (lane == 31) warpsum[w] = incl;
    __syncthreads();
    if (w == 0) {
        int s = (lane < 16) ? warpsum[lane] : 0;
#pragma unroll
        for (int d = 1; d < 16; d <<= 1) {
            int t = __shfl_up_sync(0xffffffffu, s, d);
            if (lane >= d) s += t;
        }
        if (lane < 16) warpsum[lane] = s;
    }
    __syncthreads();
    int total = warpsum[15];
    incl += (w > 0) ? warpsum[w - 1] : 0;

    if (tid == 0)
        atomicExch(&d_scanstate[bid],
                   ((unsigned long long)total << 2) | (bid == 0 ? 2ULL : 1ULL));

    if (w == 0) {
        int pref = 0;
        if (bid > 0) {
            int j = bid - 1;
            while (true) {
                int idx = j - (int)lane;
                unsigned long long st;
                if (idx >= 0) {
                    do { st = atomicAdd(&d_scanstate[idx], 0ULL); } while ((st & 3ULL) == 0ULL);
                } else {
                    st = 2ULL;
                }
                unsigned pmask = __ballot_sync(0xffffffffu, (st & 3ULL) == 2ULL);
                int val = (int)(st >> 2);
                int contrib;
                if (pmask) {
                    int k = __ffs(pmask) - 1;
                    contrib = (lane <= k) ? val : 0;
                } else {
                    contrib = val;
                }
#pragma unroll
                for (int o = 16; o; o >>= 1) contrib += __shfl_xor_sync(0xffffffffu, contrib, o);
                pref += contrib;
                if (pmask) break;
                j -= 32;
            }
            if (lane == 0)
                atomicExch(&d_scanstate[bid],
                           ((unsigned long long)(pref + total) << 2) | 2ULL);
        }
        if (lane == 0) spref = pref;
    }
    __syncthreads();

    int ex = spref + incl - deg;
    if (i < n) {
        d_off[i] = ex;
        d_pos[i] = ex;
        d_dinv[i] = rsqrtf(1.0f + (float)deg);
    }
    if (i == n - 1) d_off[n] = e;
}

// ================= CSR fill (4 edges/thread) =================
__global__ void k_fill4(const int* __restrict__ src, const int* __restrict__ dst, int e) {
    int i = (blockIdx.x * blockDim.x + threadIdx.x) * 4;
    if (i + 4 <= e) {
        int4 s = *(const int4*)(src + i);
        int4 d = *(const int4*)(dst + i);
        int p0 = atomicAdd(&d_pos[d.x], 1); d_csr[p0] = s.x;
        int p1 = atomicAdd(&d_pos[d.y], 1); d_csr[p1] = s.y;
        int p2 = atomicAdd(&d_pos[d.z], 1); d_csr[p2] = s.z;
        int p3 = atomicAdd(&d_pos[d.w], 1); d_csr[p3] = s.w;
    } else {
        for (; i < e; ++i) {
            int d = dst[i];
            int p = atomicAdd(&d_pos[d], 1);
            d_csr[p] = src[i];
        }
    }
}

// ================= tf32 helpers =================
__device__ __forceinline__ float f2tf32(float f) {
    unsigned u;
    asm("cvt.rna.tf32.f32 %0, %1;\n" : "=r"(u) : "f"(f));
    return __uint_as_float(u);
}

__device__ __forceinline__ void mma_tf32(float* d,
                                         const unsigned* a, const unsigned* b,
                                         const float* c) {
    asm volatile(
        "mma.sync.aligned.m16n8k8.row.col.f32.tf32.tf32.f32 "
        "{%0,%1,%2,%3}, {%4,%5,%6,%7}, {%8,%9}, {%10,%11,%12,%13};\n"
        : "=f"(d[0]), "=f"(d[1]), "=f"(d[2]), "=f"(d[3])
        : "r"(a[0]), "r"(a[1]), "r"(a[2]), "r"(a[3]),
          "r"(b[0]), "r"(b[1]),
          "f"(c[0]), "f"(c[1]), "f"(c[2]), "f"(c[3]));
}

// ================= GEMM1 (tf32 mma.sync, double-buffered): g1 = x @ W1 =====
// Writes UNSCALED product (no dinv dependency -> can start at t=0).
// 128 nodes x 64 cols / block; 8 warps 4(m) x 2(n); register prefetch of the
// next k-chunk overlaps the MMA block on the current chunk.
#define G1_LDA 36   // xs stride: bank = 4*row + k (mod 32), conflict-free
#define G1_LDB 72   // ws stride: bank = 8*k + n (mod 32), conflict-free
__global__ __launch_bounds__(256) void k_gemm1(const float* __restrict__ x,
                                               const float* __restrict__ W, int n) {
    __shared__ float xs[128 * G1_LDA];  // 128 rows x 32 k
    __shared__ float ws[32 * G1_LDB];   // 32 k x 64 n
    int tid = threadIdx.x;
    int w = tid >> 5, lane = tid & 31;
    int g = lane >> 2, t = lane & 3;
    int nodeBase = blockIdx.x * 128;
    int mw = (w & 3) * 32;
    int nw = (w >> 2) * 32;

    float acc[2][4][4] = {};
    float4 xr[4], wr[2];

    // preload chunk 0 into registers
#pragma unroll
    for (int i = 0; i < 4; ++i) {
        int flat = i * 256 + tid;
        int row = flat >> 3, c4 = flat & 7;
        int node = nodeBase + row;
        xr[i] = make_float4(0.f, 0.f, 0.f, 0.f);
        if (node < n) xr[i] = __ldg((const float4*)(x + (size_t)node * F0 + 4 * c4));
    }
#pragma unroll
    for (int i = 0; i < 2; ++i) {
        int flat = i * 256 + tid;
        int row = flat >> 4, c4 = flat & 15;
        wr[i] = __ldg((const float4*)(W + (size_t)row * F1 + 4 * c4));
    }

#pragma unroll
    for (int kcc = 0; kcc < 4; ++kcc) {
        // store current chunk to smem (cvt to tf32 here)
#pragma unroll
        for (int i = 0; i < 4; ++i) {
            int flat = i * 256 + tid;
            int row = flat >> 3, c4 = flat & 7;
            float4 v = xr[i];
            v.x = f2tf32(v.x); v.y = f2tf32(v.y);
            v.z = f2tf32(v.z); v.w = f2tf32(v.w);
            *(float4*)&xs[row * G1_LDA + 4 * c4] = v;
        }
#pragma unroll
        for (int i = 0; i < 2; ++i) {
            int flat = i * 256 + tid;
            int row = flat >> 4, c4 = flat & 15;
            float4 v = wr[i];
            v.x = f2tf32(v.x); v.y = f2tf32(v.y);
            v.z = f2tf32(v.z); v.w = f2tf32(v.w);
            *(float4*)&ws[row * G1_LDB + 4 * c4] = v;
        }
        __syncthreads();

        // prefetch next chunk (LDGs in flight during the MMA block below)
        if (kcc < 3) {
            int kc = (kcc + 1) * 32;
#pragma unroll
            for (int i = 0; i < 4; ++i) {
                int flat = i * 256 + tid;
                int row = flat >> 3, c4 = flat & 7;
                int node = nodeBase + row;
                xr[i] = make_float4(0.f, 0.f, 0.f, 0.f);
                if (node < n) xr[i] = __ldg((const float4*)(x + (size_t)node * F0 + kc + 4 * c4));
            }
#pragma unroll
            for (int i = 0; i < 2; ++i) {
                int flat = i * 256 + tid;
                int row = flat >> 4, c4 = flat & 15;
                wr[i] = __ldg((const float4*)(W + (size_t)(kc + row) * F1 + 4 * c4));
            }
        }

#pragma unroll
        for (int ks = 0; ks < 4; ++ks) {
            int k0 = ks * 8;
            unsigned a[2][4];
#pragma unroll
            for (int m = 0; m < 2; ++m) {
                const float* base = &xs[(mw + 16 * m + g) * G1_LDA + k0 + t];
                a[m][0] = __float_as_uint(base[0]);
                a[m][1] = __float_as_uint(base[8 * G1_LDA]);
                a[m][2] = __float_as_uint(base[4]);
                a[m][3] = __float_as_uint(base[8 * G1_LDA + 4]);
            }
#pragma unroll
            for (int nn = 0; nn < 4; ++nn) {
                int n0 = nw + 8 * nn;
                unsigned b[2];
                b[0] = __float_as_uint(ws[(k0 + t) * G1_LDB + n0 + g]);
                b[1] = __float_as_uint(ws[(k0 + t + 4) * G1_LDB + n0 + g]);
                mma_tf32(acc[0][nn], a[0], b, acc[0][nn]);
                mma_tf32(acc[1][nn], a[1], b, acc[1][nn]);
            }
        }
        __syncthreads();
    }

    // epilogue: registers -> gmem (unscaled)
#pragma unroll
    for (int m = 0; m < 2; ++m) {
        int r0 = nodeBase + mw + 16 * m + g;
        int r1 = r0 + 8;
#pragma unroll
        for (int nn = 0; nn < 4; ++nn) {
            int col = nw + 8 * nn + 2 * t;
            if (r0 < n) {
                float2 o = make_float2(acc[m][nn][0], acc[m][nn][1]);
                *(float2*)(d_g1 + (size_t)r0 * F1 + col) = o;
            }
            if (r1 < n) {
                float2 o = make_float2(acc[m][nn][2], acc[m][nn][3]);
                *(float2*)(d_g1 + (size_t)r1 * F1 + col) = o;
            }
        }
    }
}

// ================= Gather layer1 =================
// h1[d] = relu(dinv[d]*(sum_s dinv[s]*g1[s] + dinv[d]*g1[d]) + b1)
// g1 UNSCALED; dinv[s] is a broadcast scalar per edge (16-lane group).
__global__ void k_gather1(const float* __restrict__ b1, int n) {
    int node = (blockIdx.x * blockDim.x + threadIdx.x) >> 4;
    int lane = threadIdx.x & 15;
    if (node >= n) return;
    const float4* g1 = (const float4*)d_g1;
    float dv = __ldg(&d_dinv[node]);
    float4 sv = __ldg(&g1[(size_t)node * 16 + lane]);  // self loop
    float4 acc = make_float4(sv.x * dv, sv.y * dv, sv.z * dv, sv.w * dv);
    int beg = __ldg(&d_off[node]), end = __ldg(&d_off[node + 1]);
    int j = beg;
    for (; j + 4 <= end; j += 4) {
        int s0 = __ldg(&d_csr[j + 0]);
        int s1 = __ldg(&d_csr[j + 1]);
        int s2 = __ldg(&d_csr[j + 2]);
        int s3 = __ldg(&d_csr[j + 3]);
        float w0 = __ldg(&d_dinv[s0]);
        float w1 = __ldg(&d_dinv[s1]);
        float w2 = __ldg(&d_dinv[s2]);
        float w3 = __ldg(&d_dinv[s3]);
        float4 v0 = __ldg(&g1[(size_t)s0 * 16 + lane]);
        float4 v1 = __ldg(&g1[(size_t)s1 * 16 + lane]);
        float4 v2 = __ldg(&g1[(size_t)s2 * 16 + lane]);
        float4 v3 = __ldg(&g1[(size_t)s3 * 16 + lane]);
        acc.x = fmaf(v0.x, w0, fmaf(v1.x, w1, fmaf(v2.x, w2, fmaf(v3.x, w3, acc.x))));
        acc.y = fmaf(v0.y, w0, fmaf(v1.y, w1, fmaf(v2.y, w2, fmaf(v3.y, w3, acc.y))));
        acc.z = fmaf(v0.z, w0, fmaf(v1.z, w1, fmaf(v2.z, w2, fmaf(v3.z, w3, acc.z))));
        acc.w = fmaf(v0.w, w0, fmaf(v1.w, w1, fmaf(v2.w, w2, fmaf(v3.w, w3, acc.w))));
    }
    for (; j < end; ++j) {
        int s = __ldg(&d_csr[j]);
        float wv = __ldg(&d_dinv[s]);
        float4 v = __ldg(&g1[(size_t)s * 16 + lane]);
        acc.x = fmaf(v.x, wv, acc.x);
        acc.y = fmaf(v.y, wv, acc.y);
        acc.z = fmaf(v.z, wv, acc.z);
        acc.w = fmaf(v.w, wv, acc.w);
    }
    float4 bb = __ldg(&((const float4*)b1)[lane]);
    float4 h;
    h.x = fmaxf(fmaf(acc.x, dv, bb.x), 0.f);
    h.y = fmaxf(fmaf(acc.y, dv, bb.y), 0.f);
    h.z = fmaxf(fmaf(acc.z, dv, bb.z), 0.f);
    h.w = fmaxf(fmaf(acc.w, dv, bb.w), 0.f);
    ((float4*)d_h1)[(size_t)node * 16 + lane] = h;
}

// ================= GEMM2 (fp32 SIMT, proven): g2 = (h1 @ W2) * dinv =======
__global__ void k_gemm2(const float* __restrict__ W2, int n) {
    __shared__ float4 xs4[64 * 33];
    __shared__ float  ws[64][36];
    int tid = threadIdx.x;
    int tx = tid & 15, ty = tid >> 4;
    int nodeBase = blockIdx.x * 128;
    float acc[8][2] = {};

#pragma unroll
    for (int i = 0; i < 8; ++i) {
        int flat = i * 256 + tid;
        int row = flat >> 4;
        int c4  = flat & 15;
        int node = nodeBase + row;
        float4 v = make_float4(0.f, 0.f, 0.f, 0.f);
        if (node < n) v = __ldg((const float4*)(d_h1 + (size_t)node * F1 + 4 * c4));
        int g = row >> 2, el = row & 3;
        const float vv[4] = {v.x, v.y, v.z, v.w};
#pragma unroll
        for (int j = 0; j < 4; ++j) {
            int k = 4 * c4 + j;
            float* p = (float*)&xs4[k * 33 + (g ^ ((k >> 2) & 7))];
            p[el] = vv[j];
        }
    }
#pragma unroll
    for (int i = 0; i < 2; ++i) {
        int flat = i * 256 + tid;
        int k = flat >> 3;
        int c4 = flat & 7;
        float4 w = __ldg((const float4*)(W2 + (size_t)k * F2 + 4 * c4));
        *(float4*)&ws[k][4 * c4] = w;
    }
    __syncthreads();

#pragma unroll
    for (int k = 0; k < 64; ++k) {
        int swz = (k >> 2) & 7;
        float4 A0 = xs4[k * 33 + ((2 * ty) ^ swz)];
        float4 A1 = xs4[k * 33 + ((2 * ty + 1) ^ swz)];
        float b0 = ws[k][2 * tx + 0];
        float b1 = ws[k][2 * tx + 1];
        float a[8] = {A0.x, A0.y, A0.z, A0.w, A1.x, A1.y, A1.z, A1.w};
#pragma unroll
        for (int m = 0; m < 8; ++m) {
            acc[m][0] += a[m] * b0;
            acc[m][1] += a[m] * b1;
        }
    }

#pragma unroll
    for (int m = 0; m < 8; ++m) {
        int node = nodeBase + 8 * ty + m;
        if (node < n) {
            float dv = __ldg(&d_dinv[node]);
            float2 o = make_float2(acc[m][0] * dv, acc[m][1] * dv);
            *(float2*)(d_g2 + (size_t)node * F2 + 2 * tx) = o;
        }
    }
}

// ================= Gather layer2 =================
// out[d] = dinv[d]*(sum_s g2[s] + g2[d]) + b2 ; g2 prescaled by dinv[s].
__global__ void k_gather2(const float* __restrict__ b2, float* __restrict__ out, int n) {
    int node = (blockIdx.x * blockDim.x + threadIdx.x) >> 4;
    int lane = threadIdx.x & 15;
    if (node >= n) return;
    const float2* g2 = (const float2*)d_g2;
    float2 acc = __ldg(&g2[(size_t)node * 16 + lane]);
    int beg = __ldg(&d_off[node]), end = __ldg(&d_off[node + 1]);
    int j = beg;
    for (; j + 4 <= end; j += 4) {
        int s0 = __ldg(&d_csr[j + 0]);
        int s1 = __ldg(&d_csr[j + 1]);
        int s2 = __ldg(&d_csr[j + 2]);
        int s3 = __ldg(&d_csr[j + 3]);
        float2 v0 = __ldg(&g2[(size_t)s0 * 16 + lane]);
        float2 v1 = __ldg(&g2[(size_t)s1 * 16 + lane]);
        float2 v2 = __ldg(&g2[(size_t)s2 * 16 + lane]);
        float2 v3 = __ldg(&g2[(size_t)s3 * 16 + lane]);
        acc.x += (v0.x + v1.x) + (v2.x + v3.x);
        acc.y += (v0.y + v1.y) + (v2.y + v3.y);
    }
    for (; j < end; ++j) {
        int s = __ldg(&d_csr[j]);
        float2 v = __ldg(&g2[(size_t)s * 16 + lane]);
        acc.x += v.x;
        acc.y += v.y;
    }
    float dv = __ldg(&d_dinv[node]);
    float2 bb = __ldg(&((const float2*)b2)[lane]);
    float2 o;
    o.x = fmaf(acc.x, dv, bb.x);
    o.y = fmaf(acc.y, dv, bb.y);
    ((float2*)out)[(size_t)node * 16 + lane] = o;
}

extern "C" void kernel_launch(void* const* d_in, const int* in_sizes, int n_in,
                              void* d_out, int out_size) {
    const float* x  = (const float*)d_in[0];
    const int*   ei = (const int*)d_in[1];
    const float* W1 = (const float*)d_in[2];
    const float* b1 = (const float*)d_in[3];
    const float* W2 = (const float*)d_in[4];
    const float* b2 = (const float*)d_in[5];
    float* out = (float*)d_out;

    int n = in_sizes[0] / F0;   // 100000
    int e = in_sizes[1] / 2;    // 1600000
    const int* src = ei;
    const int* dst = ei + e;
    int nb = (n + 511) / 512;   // 196
    int eg4 = (e / 4 + 255) / 256 + 1;

    // Fork gemm1 immediately (no dependencies at all now).
    cudaEventRecord(g_ss.evA, 0);
    cudaStreamWaitEvent(g_ss.s, g_ss.evA, 0);
    k_gemm1<<<(n + 127) / 128, 256, 0, g_ss.s>>>(x, W1, n);
    cudaEventRecord(g_ss.evB, g_ss.s);

    // CSR build concurrently on main stream.
    k_zero<<<(n + 255) / 256, 256>>>(n, nb);
    k_count4<<<eg4, 256>>>(dst, e);
    k_scanLB<<<nb, 512>>>(n, e);
    k_fill4<<<eg4, 256>>>(src, dst, e);

    cudaStreamWaitEvent(0, g_ss.evB, 0);

    k_gather1<<<(n + 15) / 16, 256>>>(b1, n);
    k_gemm2<<<(n + 127) / 128, 256>>>(W2, n);
    k_gather2<<<(n + 15) / 16, 256>>>(b2, out, n);
}

// round 16
// speedup vs baseline: 1.1849x; 1.1109x over previous
#include <cuda_runtime.h>
#include <cuda_fp16.h>
#include <cstdint>

#define NODES 100000
#define EMAX  1600000
#define F0 128
#define F1 64
#define F2 32
#define NB_SCAN 196          // ceil(100000/512)

// ---- scratch (static device globals: allocation-free) ----
__device__ int      d_degi[NODES];
__device__ unsigned long long d_scanstate[NB_SCAN];
__device__ int      d_ticket;
__device__ int      d_off[NODES + 1];
__device__ int      d_pos[NODES];
__device__ int      d_csr[EMAX];
__device__ float    d_dinv[NODES];
__device__ unsigned d_g1h[(size_t)NODES * F1 / 2];  // x@W1 UNSCALED, packed half2
__device__ float    d_h1[(size_t)NODES * F1];       // relu layer-1 output (fp32)
__device__ unsigned d_g2h[(size_t)NODES * F2 / 2];  // (h1@W2)*dinv, packed half2

struct SideStream {
    cudaStream_t s;
    cudaEvent_t evA, evB;
    SideStream() {
        cudaStreamCreateWithFlags(&s, cudaStreamNonBlocking);
        cudaEventCreateWithFlags(&evA, cudaEventDisableTiming);
        cudaEventCreateWithFlags(&evB, cudaEventDisableTiming);
    }
};
static SideStream g_ss;

// ================= zero degree + scan state =================
__global__ void k_zero(int n, int nb) {
    int i = blockIdx.x * blockDim.x + threadIdx.x;
    if (i < n) d_degi[i] = 0;
    if (i < nb) d_scanstate[i] = 0ULL;
    if (i == 0) d_ticket = 0;
}

// ================= degree histogram (4 edges/thread) =================
__global__ void k_count4(const int* __restrict__ dst, int e) {
    int i = (blockIdx.x * blockDim.x + threadIdx.x) * 4;
    if (i + 4 <= e) {
        int4 d = *(const int4*)(dst + i);
        atomicAdd(&d_degi[d.x], 1);
        atomicAdd(&d_degi[d.y], 1);
        atomicAdd(&d_degi[d.z], 1);
        atomicAdd(&d_degi[d.w], 1);
    } else {
        for (; i < e; ++i) atomicAdd(&d_degi[dst[i]], 1);
    }
}

// ================= single-pass scan: decoupled lookback =================
__global__ void k_scanLB(int n, int e) {
    __shared__ int sbid, spref;
    __shared__ int warpsum[16];
    int tid = threadIdx.x, lane = tid & 31, w = tid >> 5;
    if (tid == 0) sbid = atomicAdd(&d_ticket, 1);
    __syncthreads();
    int bid = sbid;
    int i = bid * 512 + tid;
    int deg = (i < n) ? d_degi[i] : 0;

    int incl = deg;
#pragma unroll
    for (int d = 1; d < 32; d <<= 1) {
        int t = __shfl_up_sync(0xffffffffu, incl, d);
        if (lane >= d) incl += t;
    }
    if (lane == 31) warpsum[w] = incl;
    __syncthreads();
    if (w == 0) {
        int s = (lane < 16) ? warpsum[lane] : 0;
#pragma unroll
        for (int d = 1; d < 16; d <<= 1) {
            int t = __shfl_up_sync(0xffffffffu, s, d);
            if (lane >= d) s += t;
        }
        if (lane < 16) warpsum[lane] = s;
    }
    __syncthreads();
    int total = warpsum[15];
    incl += (w > 0) ? warpsum[w - 1] : 0;

    if (tid == 0)
        atomicExch(&d_scanstate[bid],
                   ((unsigned long long)total << 2) | (bid == 0 ? 2ULL : 1ULL));

    if (w == 0) {
        int pref = 0;
        if (bid > 0) {
            int j = bid - 1;
            while (true) {
                int idx = j - (int)lane;
                unsigned long long st;
                if (idx >= 0) {
                    do { st = atomicAdd(&d_scanstate[idx], 0ULL); } while ((st & 3ULL) == 0ULL);
                } else {
                    st = 2ULL;
                }
                unsigned pmask = __ballot_sync(0xffffffffu, (st & 3ULL) == 2ULL);
                int val = (int)(st >> 2);
                int contrib;
                if (pmask) {
                    int k = __ffs(pmask) - 1;
                    contrib = (lane <= k) ? val : 0;
                } else {
                    contrib = val;
                }
#pragma unroll
                for (int o = 16; o; o >>= 1) contrib += __shfl_xor_sync(0xffffffffu, contrib, o);
                pref += contrib;
                if (pmask) break;
                j -= 32;
            }
            if (lane == 0)
                atomicExch(&d_scanstate[bid],
                           ((unsigned long long)(pref + total) << 2) | 2ULL);
        }
        if (lane == 0) spref = pref;
    }
    __syncthreads();

    int ex = spref + incl - deg;
    if (i < n) {
        d_off[i] = ex;
        d_pos[i] = ex;
        d_dinv[i] = rsqrtf(1.0f + (float)deg);
    }
    if (i == n - 1) d_off[n] = e;
}

// ================= CSR fill (4 edges/thread) =================
__global__ void k_fill4(const int* __restrict__ src, const int* __restrict__ dst, int e) {
    int i = (blockIdx.x * blockDim.x + threadIdx.x) * 4;
    if (i + 4 <= e) {
        int4 s = *(const int4*)(src + i);
        int4 d = *(const int4*)(dst + i);
        int p0 = atomicAdd(&d_pos[d.x], 1); d_csr[p0] = s.x;
        int p1 = atomicAdd(&d_pos[d.y], 1); d_csr[p1] = s.y;
        int p2 = atomicAdd(&d_pos[d.z], 1); d_csr[p2] = s.z;
        int p3 = atomicAdd(&d_pos[d.w], 1); d_csr[p3] = s.w;
    } else {
        for (; i < e; ++i) {
            int d = dst[i];
            int p = atomicAdd(&d_pos[d], 1);
            d_csr[p] = src[i];
        }
    }
}

// ================= tf32 / half helpers =================
__device__ __forceinline__ float f2tf32(float f) {
    unsigned u;
    asm("cvt.rna.tf32.f32 %0, %1;\n" : "=r"(u) : "f"(f));
    return __uint_as_float(u);
}

__device__ __forceinline__ void mma_tf32(float* d,
                                         const unsigned* a, const unsigned* b,
                                         const float* c) {
    asm volatile(
        "mma.sync.aligned.m16n8k8.row.col.f32.tf32.tf32.f32 "
        "{%0,%1,%2,%3}, {%4,%5,%6,%7}, {%8,%9}, {%10,%11,%12,%13};\n"
        : "=f"(d[0]), "=f"(d[1]), "=f"(d[2]), "=f"(d[3])
        : "r"(a[0]), "r"(a[1]), "r"(a[2]), "r"(a[3]),
          "r"(b[0]), "r"(b[1]),
          "f"(c[0]), "f"(c[1]), "f"(c[2]), "f"(c[3]));
}

__device__ __forceinline__ unsigned pack_h2(float a, float b) {
    __half2 h = __floats2half2_rn(a, b);
    return *(unsigned*)&h;
}
__device__ __forceinline__ float2 h2f(unsigned u) {
    return __half22float2(*(__half2*)&u);
}

// ================= GEMM1 (tf32 mma.sync, double-buffered): g1 = x @ W1 =====
// Writes UNSCALED product as packed half2 (dinv applied in gather1).
#define G1_LDA 36
#define G1_LDB 72
__global__ __launch_bounds__(256) void k_gemm1(const float* __restrict__ x,
                                               const float* __restrict__ W, int n) {
    __shared__ float xs[128 * G1_LDA];
    __shared__ float ws[32 * G1_LDB];
    int tid = threadIdx.x;
    int w = tid >> 5, lane = tid & 31;
    int g = lane >> 2, t = lane & 3;
    int nodeBase = blockIdx.x * 128;
    int mw = (w & 3) * 32;
    int nw = (w >> 2) * 32;

    float acc[2][4][4] = {};
    float4 xr[4], wr[2];

#pragma unroll
    for (int i = 0; i < 4; ++i) {
        int flat = i * 256 + tid;
        int row = flat >> 3, c4 = flat & 7;
        int node = nodeBase + row;
        xr[i] = make_float4(0.f, 0.f, 0.f, 0.f);
        if (node < n) xr[i] = __ldg((const float4*)(x + (size_t)node * F0 + 4 * c4));
    }
#pragma unroll
    for (int i = 0; i < 2; ++i) {
        int flat = i * 256 + tid;
        int row = flat >> 4, c4 = flat & 15;
        wr[i] = __ldg((const float4*)(W + (size_t)row * F1 + 4 * c4));
    }

#pragma unroll
    for (int kcc = 0; kcc < 4; ++kcc) {
#pragma unroll
        for (int i = 0; i < 4; ++i) {
            int flat = i * 256 + tid;
            int row = flat >> 3, c4 = flat & 7;
            float4 v = xr[i];
            v.x = f2tf32(v.x); v.y = f2tf32(v.y);
            v.z = f2tf32(v.z); v.w = f2tf32(v.w);
            *(float4*)&xs[row * G1_LDA + 4 * c4] = v;
        }
#pragma unroll
        for (int i = 0; i < 2; ++i) {
            int flat = i * 256 + tid;
            int row = flat >> 4, c4 = flat & 15;
            float4 v = wr[i];
            v.x = f2tf32(v.x); v.y = f2tf32(v.y);
            v.z = f2tf32(v.z); v.w = f2tf32(v.w);
            *(float4*)&ws[row * G1_LDB + 4 * c4] = v;
        }
        __syncthreads();

        if (kcc < 3) {
            int kc = (kcc + 1) * 32;
#pragma unroll
            for (int i = 0; i < 4; ++i) {
                int flat = i * 256 + tid;
                int row = flat >> 3, c4 = flat & 7;
                int node = nodeBase + row;
                xr[i] = make_float4(0.f, 0.f, 0.f, 0.f);
                if (node < n) xr[i] = __ldg((const float4*)(x + (size_t)node * F0 + kc + 4 * c4));
            }
#pragma unroll
            for (int i = 0; i < 2; ++i) {
                int flat = i * 256 + tid;
                int row = flat >> 4, c4 = flat & 15;
                wr[i] = __ldg((const float4*)(W + (size_t)(kc + row) * F1 + 4 * c4));
            }
        }

#pragma unroll
        for (int ks = 0; ks < 4; ++ks) {
            int k0 = ks * 8;
            unsigned a[2][4];
#pragma unroll
            for (int m = 0; m < 2; ++m) {
                const float* base = &xs[(mw + 16 * m + g) * G1_LDA + k0 + t];
                a[m][0] = __float_as_uint(base[0]);
                a[m][1] = __float_as_uint(base[8 * G1_LDA]);
                a[m][2] = __float_as_uint(base[4]);
                a[m][3] = __float_as_uint(base[8 * G1_LDA + 4]);
            }
#pragma unroll
            for (int nn = 0; nn < 4; ++nn) {
                int n0 = nw + 8 * nn;
                unsigned b[2];
                b[0] = __float_as_uint(ws[(k0 + t) * G1_LDB + n0 + g]);
                b[1] = __float_as_uint(ws[(k0 + t + 4) * G1_LDB + n0 + g]);
                mma_tf32(acc[0][nn], a[0], b, acc[0][nn]);
                mma_tf32(acc[1][nn], a[1], b, acc[1][nn]);
            }
        }
        __syncthreads();
    }

    // epilogue: pack half2, unscaled
#pragma unroll
    for (int m = 0; m < 2; ++m) {
        int r0 = nodeBase + mw + 16 * m + g;
        int r1 = r0 + 8;
#pragma unroll
        for (int nn = 0; nn < 4; ++nn) {
            int h2col = (nw + 8 * nn) / 2 + t;   // half2 index within row (0..31)
            if (r0 < n) d_g1h[(size_t)r0 * 32 + h2col] = pack_h2(acc[m][nn][0], acc[m][nn][1]);
            if (r1 < n) d_g1h[(size_t)r1 * 32 + h2col] = pack_h2(acc[m][nn][2], acc[m][nn][3]);
        }
    }
}

// ================= Gather layer1 (fp16 payload, 16 lanes/node) =============
// h1[d] = relu(dinv[d]*(sum_s dinv[s]*g1[s] + dinv[d]*g1[d]) + b1)
__global__ void k_gather1(const float* __restrict__ b1, int n) {
    int node = (blockIdx.x * blockDim.x + threadIdx.x) >> 4;
    int lane = threadIdx.x & 15;
    if (node >= n) return;
    const uint2* g1 = (const uint2*)d_g1h;  // 8 uint2 per row... row=32 unsigned=16 uint2
    float dv = __ldg(&d_dinv[node]);
    float4 acc;
    {
        uint2 u = __ldg(&g1[(size_t)node * 16 + lane]);
        float2 f0 = h2f(u.x), f1 = h2f(u.y);
        acc = make_float4(f0.x * dv, f0.y * dv, f1.x * dv, f1.y * dv);
    }
    int beg = __ldg(&d_off[node]), end = __ldg(&d_off[node + 1]);
    int j = beg;
    for (; j + 4 <= end; j += 4) {
        int s0 = __ldg(&d_csr[j + 0]);
        int s1 = __ldg(&d_csr[j + 1]);
        int s2 = __ldg(&d_csr[j + 2]);
        int s3 = __ldg(&d_csr[j + 3]);
        float w0 = __ldg(&d_dinv[s0]);
        float w1 = __ldg(&d_dinv[s1]);
        float w2 = __ldg(&d_dinv[s2]);
        float w3 = __ldg(&d_dinv[s3]);
        uint2 u0 = __ldg(&g1[(size_t)s0 * 16 + lane]);
        uint2 u1 = __ldg(&g1[(size_t)s1 * 16 + lane]);
        uint2 u2 = __ldg(&g1[(size_t)s2 * 16 + lane]);
        uint2 u3 = __ldg(&g1[(size_t)s3 * 16 + lane]);
        float2 a0 = h2f(u0.x), b0 = h2f(u0.y);
        float2 a1 = h2f(u1.x), b1v = h2f(u1.y);
        float2 a2 = h2f(u2.x), b2v = h2f(u2.y);
        float2 a3 = h2f(u3.x), b3v = h2f(u3.y);
        acc.x = fmaf(a0.x, w0, fmaf(a1.x, w1, fmaf(a2.x, w2, fmaf(a3.x, w3, acc.x))));
        acc.y = fmaf(a0.y, w0, fmaf(a1.y, w1, fmaf(a2.y, w2, fmaf(a3.y, w3, acc.y))));
        acc.z = fmaf(b0.x, w0, fmaf(b1v.x, w1, fmaf(b2v.x, w2, fmaf(b3v.x, w3, acc.z))));
        acc.w = fmaf(b0.y, w0, fmaf(b1v.y, w1, fmaf(b2v.y, w2, fmaf(b3v.y, w3, acc.w))));
    }
    for (; j < end; ++j) {
        int s = __ldg(&d_csr[j]);
        float wv = __ldg(&d_dinv[s]);
        uint2 u = __ldg(&g1[(size_t)s * 16 + lane]);
        float2 f0 = h2f(u.x), f1 = h2f(u.y);
        acc.x = fmaf(f0.x, wv, acc.x);
        acc.y = fmaf(f0.y, wv, acc.y);
        acc.z = fmaf(f1.x, wv, acc.z);
        acc.w = fmaf(f1.y, wv, acc.w);
    }
    float4 bb = __ldg(&((const float4*)b1)[lane]);
    float4 h;
    h.x = fmaxf(fmaf(acc.x, dv, bb.x), 0.f);
    h.y = fmaxf(fmaf(acc.y, dv, bb.y), 0.f);
    h.z = fmaxf(fmaf(acc.z, dv, bb.z), 0.f);
    h.w = fmaxf(fmaf(acc.w, dv, bb.w), 0.f);
    ((float4*)d_h1)[(size_t)node * 16 + lane] = h;
}

// ================= GEMM2 (tf32 mma.sync): g2 = (h1 @ W2) * dinv, fp16 out ==
// 128 nodes x 32 cols / block; 8 warps 4(m) x 2(n); each warp 32x16 via
// 2(m) x 2(n) m16n8k8 atoms. K=64 in 2 chunks of 32.
#define G2_LDA 36
#define G2_LDB 40
__global__ __launch_bounds__(256) void k_gemm2(const float* __restrict__ W2, int n) {
    __shared__ float xs[128 * G2_LDA];
    __shared__ float ws[32 * G2_LDB];
    int tid = threadIdx.x;
    int w = tid >> 5, lane = tid & 31;
    int g = lane >> 2, t = lane & 3;
    int nodeBase = blockIdx.x * 128;
    int mw = (w & 3) * 32;
    int nw = (w >> 2) * 16;

    float acc[2][2][4] = {};

    for (int kc = 0; kc < F1; kc += 32) {
#pragma unroll
        for (int i = 0; i < 4; ++i) {
            int flat = i * 256 + tid;
            int row = flat >> 3, c4 = flat & 7;
            int node = nodeBase + row;
            float4 v = make_float4(0.f, 0.f, 0.f, 0.f);
            if (node < n) v = __ldg((const float4*)(d_h1 + (size_t)node * F1 + kc + 4 * c4));
            v.x = f2tf32(v.x); v.y = f2tf32(v.y);
            v.z = f2tf32(v.z); v.w = f2tf32(v.w);
            *(float4*)&xs[row * G2_LDA + 4 * c4] = v;
        }
        {
            int row = tid >> 3;    // 0..31
            int c4 = tid & 7;      // 0..7
            float4 v = __ldg((const float4*)(W2 + (size_t)(kc + row) * F2 + 4 * c4));
            v.x = f2tf32(v.x); v.y = f2tf32(v.y);
            v.z = f2tf32(v.z); v.w = f2tf32(v.w);
            *(float4*)&ws[row * G2_LDB + 4 * c4] = v;
        }
        __syncthreads();

#pragma unroll
        for (int ks = 0; ks < 4; ++ks) {
            int k0 = ks * 8;
            unsigned a[2][4];
#pragma unroll
            for (int m = 0; m < 2; ++m) {
                const float* base = &xs[(mw + 16 * m + g) * G2_LDA + k0 + t];
                a[m][0] = __float_as_uint(base[0]);
                a[m][1] = __float_as_uint(base[8 * G2_LDA]);
                a[m][2] = __float_as_uint(base[4]);
                a[m][3] = __float_as_uint(base[8 * G2_LDA + 4]);
            }
#pragma unroll
            for (int nn = 0; nn < 2; ++nn) {
                int n0 = nw + 8 * nn;
                unsigned b[2];
                b[0] = __float_as_uint(ws[(k0 + t) * G2_LDB + n0 + g]);
                b[1] = __float_as_uint(ws[(k0 + t + 4) * G2_LDB + n0 + g]);
                mma_tf32(acc[0][nn], a[0], b, acc[0][nn]);
                mma_tf32(acc[1][nn], a[1], b, acc[1][nn]);
            }
        }
        __syncthreads();
    }

    // epilogue: scale by dinv, pack half2
#pragma unroll
    for (int m = 0; m < 2; ++m) {
        int r0 = nodeBase + mw + 16 * m + g;
        int r1 = r0 + 8;
        float dv0 = (r0 < n) ? __ldg(&d_dinv[r0]) : 0.f;
        float dv1 = (r1 < n) ? __ldg(&d_dinv[r1]) : 0.f;
#pragma unroll
        for (int nn = 0; nn < 2; ++nn) {
            int h2col = (nw + 8 * nn) / 2 + t;   // 0..15
            if (r0 < n)
                d_g2h[(size_t)r0 * 16 + h2col] = pack_h2(acc[m][nn][0] * dv0, acc[m][nn][1] * dv0);
            if (r1 < n)
                d_g2h[(size_t)r1 * 16 + h2col] = pack_h2(acc[m][nn][2] * dv1, acc[m][nn][3] * dv1);
        }
    }
}

// ================= Gather layer2 (fp16 payload, 16 lanes/node) =============
// out[d] = dinv[d]*(sum_s g2[s] + g2[d]) + b2 ; g2 prescaled by dinv[s].
__global__ void k_gather2(const float* __restrict__ b2, float* __restrict__ out, int n) {
    int node = (blockIdx.x * blockDim.x + threadIdx.x) >> 4;
    int lane = threadIdx.x & 15;
    if (node >= n) return;
    const unsigned* g2 = d_g2h;  // 16 unsigned per row
    float2 acc;
    {
        float2 f = h2f(__ldg(&g2[(size_t)node * 16 + lane]));
        acc = f;
    }
    int beg = __ldg(&d_off[node]), end = __ldg(&d_off[node + 1]);
    int j = beg;
    for (; j + 4 <= end; j += 4) {
        int s0 = __ldg(&d_csr[j + 0]);
        int s1 = __ldg(&d_csr[j + 1]);
        int s2 = __ldg(&d_csr[j + 2]);
        int s3 = __ldg(&d_csr[j + 3]);
        unsigned u0 = __ldg(&g2[(size_t)s0 * 16 + lane]);
        unsigned u1 = __ldg(&g2[(size_t)s1 * 16 + lane]);
        unsigned u2 = __ldg(&g2[(size_t)s2 * 16 + lane]);
        unsigned u3 = __ldg(&g2[(size_t)s3 * 16 + lane]);
        float2 f0 = h2f(u0), f1 = h2f(u1), f2 = h2f(u2), f3 = h2f(u3);
        acc.x += (f0.x + f1.x) + (f2.x + f3.x);
        acc.y += (f0.y + f1.y) + (f2.y + f3.y);
    }
    for (; j < end; ++j) {
        int s = __ldg(&d_csr[j]);
        float2 f = h2f(__ldg(&g2[(size_t)s * 16 + lane]));
        acc.x += f.x;
        acc.y += f.y;
    }
    float dv = __ldg(&d_dinv[node]);
    float2 bb = __ldg(&((const float2*)b2)[lane]);
    float2 o;
    o.x = fmaf(acc.x, dv, bb.x);
    o.y = fmaf(acc.y, dv, bb.y);
    ((float2*)out)[(size_t)node * 16 + lane] = o;
}

extern "C" void kernel_launch(void* const* d_in, const int* in_sizes, int n_in,
                              void* d_out, int out_size) {
    const float* x  = (const float*)d_in[0];
    const int*   ei = (const int*)d_in[1];
    const float* W1 = (const float*)d_in[2];
    const float* b1 = (const float*)d_in[3];
    const float* W2 = (const float*)d_in[4];
    const float* b2 = (const float*)d_in[5];
    float* out = (float*)d_out;

    int n = in_sizes[0] / F0;   // 100000
    int e = in_sizes[1] / 2;    // 1600000
    const int* src = ei;
    const int* dst = ei + e;
    int nb = (n + 511) / 512;   // 196
    int eg4 = (e / 4 + 255) / 256 + 1;

    // Fork gemm1 immediately (no dependencies).
    cudaEventRecord(g_ss.evA, 0);
    cudaStreamWaitEvent(g_ss.s, g_ss.evA, 0);
    k_gemm1<<<(n + 127) / 128, 256, 0, g_ss.s>>>(x, W1, n);
    cudaEventRecord(g_ss.evB, g_ss.s);

    // CSR build concurrently on main stream.
    k_zero<<<(n + 255) / 256, 256>>>(n, nb);
    k_count4<<<eg4, 256>>>(dst, e);
    k_scanLB<<<nb, 512>>>(n, e);
    k_fill4<<<eg4, 256>>>(src, dst, e);

    cudaStreamWaitEvent(0, g_ss.evB, 0);

    k_gather1<<<(n + 15) / 16, 256>>>(b1, n);
    k_gemm2<<<(n + 127) / 128, 256>>>(W2, n);
    k_gather2<<<(n + 15) / 16, 256>>>(b2, out, n);
}

// round 17
// speedup vs baseline: 1.2045x; 1.0166x over previous
#include <cuda_runtime.h>
#include <cuda_fp16.h>
#include <cstdint>

#define NODES 100000
#define EMAX  1600000
#define F0 128
#define F1 64
#define F2 32
#define NB_SCAN 196          // ceil(100000/512)

// ---- scratch (static device globals: allocation-free) ----
__device__ int      d_degi[NODES];
__device__ unsigned long long d_scanstate[NB_SCAN];
__device__ int      d_ticket;
__device__ int      d_off[NODES + 1];
__device__ int      d_pos[NODES];
__device__ int      d_csr[EMAX];
__device__ float    d_dinv[NODES];
__device__ unsigned d_g1h[(size_t)NODES * F1 / 2];  // x@W1; prescaled by dinv[row] after k_prescale
__device__ unsigned d_h1h[(size_t)NODES * F1 / 2];  // relu layer-1 output, packed half2
__device__ unsigned d_g2h[(size_t)NODES * F2 / 2];  // (h1@W2)*dinv, packed half2

struct SideStream {
    cudaStream_t s;
    cudaEvent_t evA, evScan, evB;
    SideStream() {
        cudaStreamCreateWithFlags(&s, cudaStreamNonBlocking);
        cudaEventCreateWithFlags(&evA, cudaEventDisableTiming);
        cudaEventCreateWithFlags(&evScan, cudaEventDisableTiming);
        cudaEventCreateWithFlags(&evB, cudaEventDisableTiming);
    }
};
static SideStream g_ss;

// ================= zero degree + scan state =================
__global__ void k_zero(int n, int nb) {
    int i = blockIdx.x * blockDim.x + threadIdx.x;
    if (i < n) d_degi[i] = 0;
    if (i < nb) d_scanstate[i] = 0ULL;
    if (i == 0) d_ticket = 0;
}

// ================= degree histogram (4 edges/thread) =================
__global__ void k_count4(const int* __restrict__ dst, int e) {
    int i = (blockIdx.x * blockDim.x + threadIdx.x) * 4;
    if (i + 4 <= e) {
        int4 d = *(const int4*)(dst + i);
        atomicAdd(&d_degi[d.x], 1);
        atomicAdd(&d_degi[d.y], 1);
        atomicAdd(&d_degi[d.z], 1);
        atomicAdd(&d_degi[d.w], 1);
    } else {
        for (; i < e; ++i) atomicAdd(&d_degi[dst[i]], 1);
    }
}

// ================= single-pass scan: decoupled lookback =================
__global__ void k_scanLB(int n, int e) {
    __shared__ int sbid, spref;
    __shared__ int warpsum[16];
    int tid = threadIdx.x, lane = tid & 31, w = tid >> 5;
    if (tid == 0) sbid = atomicAdd(&d_ticket, 1);
    __syncthreads();
    int bid = sbid;
    int i = bid * 512 + tid;
    int deg = (i < n) ? d_degi[i] : 0;

    int incl = deg;
#pragma unroll
    for (int d = 1; d < 32; d <<= 1) {
        int t = __shfl_up_sync(0xffffffffu, incl, d);
        if (lane >= d) incl += t;
    }
    if (lane == 31) warpsum[w] = incl;
    __syncthreads();
    if (w == 0) {
        int s = (lane < 16) ? warpsum[lane] : 0;
#pragma unroll
        for (int d = 1; d < 16; d <<= 1) {
            int t = __shfl_up_sync(0xffffffffu, s, d);
            if (lane >= d) s += t;
        }
        if (lane < 16) warpsum[lane] = s;
    }
    __syncthreads();
    int total = warpsum[15];
    incl += (w > 0) ? warpsum[w - 1] : 0;

    if (tid == 0)
        atomicExch(&d_scanstate[bid],
                   ((unsigned long long)total << 2) | (bid == 0 ? 2ULL : 1ULL));

    if (w == 0) {
        int pref = 0;
        if (bid > 0) {
            int j = bid - 1;
            while (true) {
                int idx = j - (int)lane;
                unsigned long long st;
                if (idx >= 0) {
                    do { st = atomicAdd(&d_scanstate[idx], 0ULL); } while ((st & 3ULL) == 0ULL);
                } else {
                    st = 2ULL;
                }
                unsigned pmask = __ballot_sync(0xffffffffu, (st & 3ULL) == 2ULL);
                int val = (int)(st >> 2);
                int contrib;
                if (pmask) {
                    int k = __ffs(pmask) - 1;
                    contrib = (lane <= k) ? val : 0;
                } else {
                    contrib = val;
                }
#pragma unroll
                for (int o = 16; o; o >>= 1) contrib += __shfl_xor_sync(0xffffffffu, contrib, o);
                pref += contrib;
                if (pmask) break;
                j -= 32;
            }
            if (lane == 0)
                atomicExch(&d_scanstate[bid],
                           ((unsigned long long)(pref + total) << 2) | 2ULL);
        }
        if (lane == 0) spref = pref;
    }
    __syncthreads();

    int ex = spref + incl - deg;
    if (i < n) {
        d_off[i] = ex;
        d_pos[i] = ex;
        d_dinv[i] = rsqrtf(1.0f + (float)deg);
    }
    if (i == n - 1) d_off[n] = e;
}

// ================= CSR fill (4 edges/thread) =================
__global__ void k_fill4(const int* __restrict__ src, const int* __restrict__ dst, int e) {
    int i = (blockIdx.x * blockDim.x + threadIdx.x) * 4;
    if (i + 4 <= e) {
        int4 s = *(const int4*)(src + i);
        int4 d = *(const int4*)(dst + i);
        int p0 = atomicAdd(&d_pos[d.x], 1); d_csr[p0] = s.x;
        int p1 = atomicAdd(&d_pos[d.y], 1); d_csr[p1] = s.y;
        int p2 = atomicAdd(&d_pos[d.z], 1); d_csr[p2] = s.z;
        int p3 = atomicAdd(&d_pos[d.w], 1); d_csr[p3] = s.w;
    } else {
        for (; i < e; ++i) {
            int d = dst[i];
            int p = atomicAdd(&d_pos[d], 1);
            d_csr[p] = src[i];
        }
    }
}

// ================= tf32 / half helpers =================
__device__ __forceinline__ float f2tf32(float f) {
    unsigned u;
    asm("cvt.rna.tf32.f32 %0, %1;\n" : "=r"(u) : "f"(f));
    return __uint_as_float(u);
}

__device__ __forceinline__ void mma_tf32(float* d,
                                         const unsigned* a, const unsigned* b,
                                         const float* c) {
    asm volatile(
        "mma.sync.aligned.m16n8k8.row.col.f32.tf32.tf32.f32 "
        "{%0,%1,%2,%3}, {%4,%5,%6,%7}, {%8,%9}, {%10,%11,%12,%13};\n"
        : "=f"(d[0]), "=f"(d[1]), "=f"(d[2]), "=f"(d[3])
        : "r"(a[0]), "r"(a[1]), "r"(a[2]), "r"(a[3]),
          "r"(b[0]), "r"(b[1]),
          "f"(c[0]), "f"(c[1]), "f"(c[2]), "f"(c[3]));
}

__device__ __forceinline__ unsigned pack_h2(float a, float b) {
    __half2 h = __floats2half2_rn(a, b);
    return *(unsigned*)&h;
}
__device__ __forceinline__ float2 h2f(unsigned u) {
    return __half22float2(*(__half2*)&u);
}

// ================= GEMM1 (tf32 mma.sync, double-buffered): g1 = x @ W1 =====
// Writes UNSCALED product as packed half2; k_prescale applies dinv[row] later.
#define G1_LDA 36
#define G1_LDB 72
__global__ __launch_bounds__(256) void k_gemm1(const float* __restrict__ x,
                                               const float* __restrict__ W, int n) {
    __shared__ float xs[128 * G1_LDA];
    __shared__ float ws[32 * G1_LDB];
    int tid = threadIdx.x;
    int w = tid >> 5, lane = tid & 31;
    int g = lane >> 2, t = lane & 3;
    int nodeBase = blockIdx.x * 128;
    int mw = (w & 3) * 32;
    int nw = (w >> 2) * 32;

    float acc[2][4][4] = {};
    float4 xr[4], wr[2];

#pragma unroll
    for (int i = 0; i < 4; ++i) {
        int flat = i * 256 + tid;
        int row = flat >> 3, c4 = flat & 7;
        int node = nodeBase + row;
        xr[i] = make_float4(0.f, 0.f, 0.f, 0.f);
        if (node < n) xr[i] = __ldg((const float4*)(x + (size_t)node * F0 + 4 * c4));
    }
#pragma unroll
    for (int i = 0; i < 2; ++i) {
        int flat = i * 256 + tid;
        int row = flat >> 4, c4 = flat & 15;
        wr[i] = __ldg((const float4*)(W + (size_t)row * F1 + 4 * c4));
    }

#pragma unroll
    for (int kcc = 0; kcc < 4; ++kcc) {
#pragma unroll
        for (int i = 0; i < 4; ++i) {
            int flat = i * 256 + tid;
            int row = flat >> 3, c4 = flat & 7;
            float4 v = xr[i];
            v.x = f2tf32(v.x); v.y = f2tf32(v.y);
            v.z = f2tf32(v.z); v.w = f2tf32(v.w);
            *(float4*)&xs[row * G1_LDA + 4 * c4] = v;
        }
#pragma unroll
        for (int i = 0; i < 2; ++i) {
            int flat = i * 256 + tid;
            int row = flat >> 4, c4 = flat & 15;
            float4 v = wr[i];
            v.x = f2tf32(v.x); v.y = f2tf32(v.y);
            v.z = f2tf32(v.z); v.w = f2tf32(v.w);
            *(float4*)&ws[row * G1_LDB + 4 * c4] = v;
        }
        __syncthreads();

        if (kcc < 3) {
            int kc = (kcc + 1) * 32;
#pragma unroll
            for (int i = 0; i < 4; ++i) {
                int flat = i * 256 + tid;
                int row = flat >> 3, c4 = flat & 7;
                int node = nodeBase + row;
                xr[i] = make_float4(0.f, 0.f, 0.f, 0.f);
                if (node < n) xr[i] = __ldg((const float4*)(x + (size_t)node * F0 + kc + 4 * c4));
            }
#pragma unroll
            for (int i = 0; i < 2; ++i) {
                int flat = i * 256 + tid;
                int row = flat >> 4, c4 = flat & 15;
                wr[i] = __ldg((const float4*)(W + (size_t)(kc + row) * F1 + 4 * c4));
            }
        }

#pragma unroll
        for (int ks = 0; ks < 4; ++ks) {
            int k0 = ks * 8;
            unsigned a[2][4];
#pragma unroll
            for (int m = 0; m < 2; ++m) {
                const float* base = &xs[(mw + 16 * m + g) * G1_LDA + k0 + t];
                a[m][0] = __float_as_uint(base[0]);
                a[m][1] = __float_as_uint(base[8 * G1_LDA]);
                a[m][2] = __float_as_uint(base[4]);
                a[m][3] = __float_as_uint(base[8 * G1_LDA + 4]);
            }
#pragma unroll
            for (int nn = 0; nn < 4; ++nn) {
                int n0 = nw + 8 * nn;
                unsigned b[2];
                b[0] = __float_as_uint(ws[(k0 + t) * G1_LDB + n0 + g]);
                b[1] = __float_as_uint(ws[(k0 + t + 4) * G1_LDB + n0 + g]);
                mma_tf32(acc[0][nn], a[0], b, acc[0][nn]);
                mma_tf32(acc[1][nn], a[1], b, acc[1][nn]);
            }
        }
        __syncthreads();
    }

#pragma unroll
    for (int m = 0; m < 2; ++m) {
        int r0 = nodeBase + mw + 16 * m + g;
        int r1 = r0 + 8;
#pragma unroll
        for (int nn = 0; nn < 4; ++nn) {
            int h2col = (nw + 8 * nn) / 2 + t;
            if (r0 < n) d_g1h[(size_t)r0 * 32 + h2col] = pack_h2(acc[m][nn][0], acc[m][nn][1]);
            if (r1 < n) d_g1h[(size_t)r1 * 32 + h2col] = pack_h2(acc[m][nn][2], acc[m][nn][3]);
        }
    }
}

// ================= Prescale: g1h[row] *= dinv[row] (in place) =============
// Runs on side stream after gemm1 + scanLB; hidden behind k_fill4.
__global__ void k_prescale(int n) {
    int idx = blockIdx.x * blockDim.x + threadIdx.x;  // uint4 index; 8 per row
    if (idx >= n * 8) return;
    int node = idx >> 3;
    float dv = __ldg(&d_dinv[node]);
    uint4 u = *(uint4*)&d_g1h[(size_t)idx * 4];
    float2 f0 = h2f(u.x), f1 = h2f(u.y), f2 = h2f(u.z), f3 = h2f(u.w);
    u.x = pack_h2(f0.x * dv, f0.y * dv);
    u.y = pack_h2(f1.x * dv, f1.y * dv);
    u.z = pack_h2(f2.x * dv, f2.y * dv);
    u.w = pack_h2(f3.x * dv, f3.y * dv);
    *(uint4*)&d_g1h[(size_t)idx * 4] = u;
}

// ================= Gather layer1 (prescaled fp16 payload, pure adds) =======
// h1[d] = relu(dinv[d]*(sum_s gs[s] + gs[d]) + b1) ; gs = dinv*g1.
__global__ void k_gather1(const float* __restrict__ b1, int n) {
    int node = (blockIdx.x * blockDim.x + threadIdx.x) >> 4;
    int lane = threadIdx.x & 15;
    if (node >= n) return;
    const uint2* g1 = (const uint2*)d_g1h;  // 16 uint2 per row
    float4 acc;
    {
        uint2 u = __ldg(&g1[(size_t)node * 16 + lane]);
        float2 f0 = h2f(u.x), f1 = h2f(u.y);
        acc = make_float4(f0.x, f0.y, f1.x, f1.y);
    }
    int beg = __ldg(&d_off[node]), end = __ldg(&d_off[node + 1]);
    int j = beg;
    for (; j + 4 <= end; j += 4) {
        int s0 = __ldg(&d_csr[j + 0]);
        int s1 = __ldg(&d_csr[j + 1]);
        int s2 = __ldg(&d_csr[j + 2]);
        int s3 = __ldg(&d_csr[j + 3]);
        uint2 u0 = __ldg(&g1[(size_t)s0 * 16 + lane]);
        uint2 u1 = __ldg(&g1[(size_t)s1 * 16 + lane]);
        uint2 u2 = __ldg(&g1[(size_t)s2 * 16 + lane]);
        uint2 u3 = __ldg(&g1[(size_t)s3 * 16 + lane]);
        float2 a0 = h2f(u0.x), c0 = h2f(u0.y);
        float2 a1 = h2f(u1.x), c1 = h2f(u1.y);
        float2 a2 = h2f(u2.x), c2 = h2f(u2.y);
        float2 a3 = h2f(u3.x), c3 = h2f(u3.y);
        acc.x += (a0.x + a1.x) + (a2.x + a3.x);
        acc.y += (a0.y + a1.y) + (a2.y + a3.y);
        acc.z += (c0.x + c1.x) + (c2.x + c3.x);
        acc.w += (c0.y + c1.y) + (c2.y + c3.y);
    }
    for (; j < end; ++j) {
        int s = __ldg(&d_csr[j]);
        uint2 u = __ldg(&g1[(size_t)s * 16 + lane]);
        float2 f0 = h2f(u.x), f1 = h2f(u.y);
        acc.x += f0.x; acc.y += f0.y; acc.z += f1.x; acc.w += f1.y;
    }
    float dv = __ldg(&d_dinv[node]);
    float4 bb = __ldg(&((const float4*)b1)[lane]);
    float hx = fmaxf(fmaf(acc.x, dv, bb.x), 0.f);
    float hy = fmaxf(fmaf(acc.y, dv, bb.y), 0.f);
    float hz = fmaxf(fmaf(acc.z, dv, bb.z), 0.f);
    float hw = fmaxf(fmaf(acc.w, dv, bb.w), 0.f);
    uint2 o;
    o.x = pack_h2(hx, hy);
    o.y = pack_h2(hz, hw);
    *(uint2*)&d_h1h[(size_t)node * 32 + 2 * lane] = o;
}

// ================= GEMM2 (tf32 mma.sync, fp16 in): g2 = (h1 @ W2)*dinv =====
#define G2_LDA 36
#define G2_LDB 40
__global__ __launch_bounds__(256) void k_gemm2(const float* __restrict__ W2, int n) {
    __shared__ float xs[128 * G2_LDA];
    __shared__ float ws[32 * G2_LDB];
    int tid = threadIdx.x;
    int w = tid >> 5, lane = tid & 31;
    int g = lane >> 2, t = lane & 3;
    int nodeBase = blockIdx.x * 128;
    int mw = (w & 3) * 32;
    int nw = (w >> 2) * 16;

    float acc[2][2][4] = {};

    for (int kc = 0; kc < F1; kc += 32) {
        // stage h1 chunk (128 x 32) from fp16, cvt to tf32
#pragma unroll
        for (int i = 0; i < 4; ++i) {
            int flat = i * 256 + tid;       // 0..1023
            int row = flat >> 3;            // 0..127
            int u2c = flat & 7;             // 0..7 (uint2 = 4 halves)
            int node = nodeBase + row;
            uint2 u = make_uint2(0u, 0u);
            if (node < n) u = *(const uint2*)&d_h1h[(size_t)node * 32 + kc / 2 + 2 * u2c];
            float2 f0 = h2f(u.x), f1 = h2f(u.y);
            float4 v;
            v.x = f2tf32(f0.x); v.y = f2tf32(f0.y);
            v.z = f2tf32(f1.x); v.w = f2tf32(f1.y);
            *(float4*)&xs[row * G2_LDA + 4 * u2c] = v;
        }
        {
            int row = tid >> 3;
            int c4 = tid & 7;
            float4 v = __ldg((const float4*)(W2 + (size_t)(kc + row) * F2 + 4 * c4));
            v.x = f2tf32(v.x); v.y = f2tf32(v.y);
            v.z = f2tf32(v.z); v.w = f2tf32(v.w);
            *(float4*)&ws[row * G2_LDB + 4 * c4] = v;
        }
        __syncthreads();

#pragma unroll
        for (int ks = 0; ks < 4; ++ks) {
            int k0 = ks * 8;
            unsigned a[2][4];
#pragma unroll
            for (int m = 0; m < 2; ++m) {
                const float* base = &xs[(mw + 16 * m + g) * G2_LDA + k0 + t];
                a[m][0] = __float_as_uint(base[0]);
                a[m][1] = __float_as_uint(base[8 * G2_LDA]);
                a[m][2] = __float_as_uint(base[4]);
                a[m][3] = __float_as_uint(base[8 * G2_LDA + 4]);
            }
#pragma unroll
            for (int nn = 0; nn < 2; ++nn) {
                int n0 = nw + 8 * nn;
                unsigned b[2];
                b[0] = __float_as_uint(ws[(k0 + t) * G2_LDB + n0 + g]);
                b[1] = __float_as_uint(ws[(k0 + t + 4) * G2_LDB + n0 + g]);
                mma_tf32(acc[0][nn], a[0], b, acc[0][nn]);
                mma_tf32(acc[1][nn], a[1], b, acc[1][nn]);
            }
        }
        __syncthreads();
    }

#pragma unroll
    for (int m = 0; m < 2; ++m) {
        int r0 = nodeBase + mw + 16 * m + g;
        int r1 = r0 + 8;
        float dv0 = (r0 < n) ? __ldg(&d_dinv[r0]) : 0.f;
        float dv1 = (r1 < n) ? __ldg(&d_dinv[r1]) : 0.f;
#pragma unroll
        for (int nn = 0; nn < 2; ++nn) {
            int h2col = (nw + 8 * nn) / 2 + t;
            if (r0 < n)
                d_g2h[(size_t)r0 * 16 + h2col] = pack_h2(acc[m][nn][0] * dv0, acc[m][nn][1] * dv0);
            if (r1 < n)
                d_g2h[(size_t)r1 * 16 + h2col] = pack_h2(acc[m][nn][2] * dv1, acc[m][nn][3] * dv1);
        }
    }
}

// ================= Gather layer2 (fp16 payload, 16 lanes/node) =============
// out[d] = dinv[d]*(sum_s g2[s] + g2[d]) + b2 ; g2 prescaled by dinv[s].
__global__ void k_gather2(const float* __restrict__ b2, float* __restrict__ out, int n) {
    int node = (blockIdx.x * blockDim.x + threadIdx.x) >> 4;
    int lane = threadIdx.x & 15;
    if (node >= n) return;
    const unsigned* g2 = d_g2h;
    float2 acc = h2f(__ldg(&g2[(size_t)node * 16 + lane]));
    int beg = __ldg(&d_off[node]), end = __ldg(&d_off[node + 1]);
    int j = beg;
    for (; j + 4 <= end; j += 4) {
        int s0 = __ldg(&d_csr[j + 0]);
        int s1 = __ldg(&d_csr[j + 1]);
        int s2 = __ldg(&d_csr[j + 2]);
        int s3 = __ldg(&d_csr[j + 3]);
        unsigned u0 = __ldg(&g2[(size_t)s0 * 16 + lane]);
        unsigned u1 = __ldg(&g2[(size_t)s1 * 16 + lane]);
        unsigned u2 = __ldg(&g2[(size_t)s2 * 16 + lane]);
        unsigned u3 = __ldg(&g2[(size_t)s3 * 16 + lane]);
        float2 f0 = h2f(u0), f1 = h2f(u1), f2 = h2f(u2), f3 = h2f(u3);
        acc.x += (f0.x + f1.x) + (f2.x + f3.x);
        acc.y += (f0.y + f1.y) + (f2.y + f3.y);
    }
    for (; j < end; ++j) {
        int s = __ldg(&d_csr[j]);
        float2 f = h2f(__ldg(&g2[(size_t)s * 16 + lane]));
        acc.x += f.x;
        acc.y += f.y;
    }
    float dv = __ldg(&d_dinv[node]);
    float2 bb = __ldg(&((const float2*)b2)[lane]);
    float2 o;
    o.x = fmaf(acc.x, dv, bb.x);
    o.y = fmaf(acc.y, dv, bb.y);
    ((float2*)out)[(size_t)node * 16 + lane] = o;
}

extern "C" void kernel_launch(void* const* d_in, const int* in_sizes, int n_in,
                              void* d_out, int out_size) {
    const float* x  = (const float*)d_in[0];
    const int*   ei = (const int*)d_in[1];
    const float* W1 = (const float*)d_in[2];
    const float* b1 = (const float*)d_in[3];
    const float* W2 = (const float*)d_in[4];
    const float* b2 = (const float*)d_in[5];
    float* out = (float*)d_out;

    int n = in_sizes[0] / F0;   // 100000
    int e = in_sizes[1] / 2;    // 1600000
    const int* src = ei;
    const int* dst = ei + e;
    int nb = (n + 511) / 512;   // 196
    int eg4 = (e / 4 + 255) / 256 + 1;

    // Fork gemm1 immediately on side stream (no dependencies).
    cudaEventRecord(g_ss.evA, 0);
    cudaStreamWaitEvent(g_ss.s, g_ss.evA, 0);
    k_gemm1<<<(n + 127) / 128, 256, 0, g_ss.s>>>(x, W1, n);

    // CSR build on main stream; signal dinv availability after scanLB.
    k_zero<<<(n + 255) / 256, 256>>>(n, nb);
    k_count4<<<eg4, 256>>>(dst, e);
    k_scanLB<<<nb, 512>>>(n, e);
    cudaEventRecord(g_ss.evScan, 0);
    k_fill4<<<eg4, 256>>>(src, dst, e);

    // Side stream: prescale g1h by dinv (needs gemm1 + scanLB), hidden behind fill4.
    cudaStreamWaitEvent(g_ss.s, g_ss.evScan, 0);
    k_prescale<<<(n * 8 + 255) / 256, 256, 0, g_ss.s>>>(n);
    cudaEventRecord(g_ss.evB, g_ss.s);

    cudaStreamWaitEvent(0, g_ss.evB, 0);

    k_gather1<<<(n + 15) / 16, 256>>>(b1, n);
    k_gemm2<<<(n + 127) / 128, 256>>>(W2, n);
    k_gather2<<<(n + 15) / 16, 256>>>(b2, out, n);
}